// round 9
// baseline (speedup 1.0000x reference)
#include <cuda_runtime.h>
#include <cstdint>
#include <cstddef>
#include <math.h>

#define BB 2
#define TT 2048
#define CC 1024
#define HH 16
#define NROWS (BB*TT)   // 4096

// ---------------- scratch (static device allocations; no cudaMalloc) -------
__device__ float g_qw[CC*CC];
__device__ float g_kw[CC*CC];
__device__ float g_vw[CC*CC];
__device__ float g_pw[CC*CC];
__device__ float g_xt[NROWS*CC];
__device__ float g_q[NROWS*CC];
__device__ float g_k[NROWS*CC];
__device__ float g_v[NROWS*CC];
__device__ float g_y[NROWS*CC];
__device__ float g_ga[NROWS*HH];

__device__ __forceinline__ void cp_async16(uint32_t saddr, const void* g) {
    asm volatile("cp.async.cg.shared.global [%0], [%1], 16;\n" :: "r"(saddr), "l"(g));
}
__device__ __forceinline__ void cp_commit() {
    asm volatile("cp.async.commit_group;\n");
}
__device__ __forceinline__ void cp_wait0() {
    asm volatile("cp.async.wait_group 0;\n");
}
__device__ __forceinline__ void cp_wait1() {
    asm volatile("cp.async.wait_group 1;\n");
}
__device__ __forceinline__ uint32_t f2tf32(float x) {
    uint32_t r;
    asm("cvt.rna.tf32.f32 %0, %1;" : "=r"(r) : "f"(x));
    return r;
}
__device__ __forceinline__ void mma_tf32(float c[4], uint32_t a0, uint32_t a1,
                                         uint32_t a2, uint32_t a3,
                                         uint32_t b0, uint32_t b1) {
    asm volatile(
        "mma.sync.aligned.m16n8k8.row.col.f32.tf32.tf32.f32 "
        "{%0,%1,%2,%3}, {%4,%5,%6,%7}, {%8,%9}, {%0,%1,%2,%3};"
        : "+f"(c[0]), "+f"(c[1]), "+f"(c[2]), "+f"(c[3])
        : "r"(a0), "r"(a1), "r"(a2), "r"(a3), "r"(b0), "r"(b1));
}

// ---------------- 0) round x to tf32 ----------------------------------------
__global__ void round_x_kernel(const float* __restrict__ x) {
    int i = blockIdx.x * blockDim.x + threadIdx.x;
    float4 v = ((const float4*)x)[i];
    uint4 r = {f2tf32(v.x), f2tf32(v.y), f2tf32(v.z), f2tf32(v.w)};
    ((uint4*)g_xt)[i] = r;
}

// ---------------- 1) fuse mix into weights (tf32-rounded); wi=3 rounds cpw --
__global__ void fuse_kernel(const float* __restrict__ cq, const float* __restrict__ ck,
                            const float* __restrict__ cv, const float* __restrict__ cp,
                            const float* __restrict__ qm,
                            const float* __restrict__ km, const float* __restrict__ vm) {
    int row = blockIdx.x;
    int wi  = blockIdx.y;
    if (wi == 3) {
        int c = threadIdx.x * 4;
        float4 v = *(const float4*)&cp[row*CC + c];
        uint4 r = {f2tf32(v.x), f2tf32(v.y), f2tf32(v.z), f2tf32(v.w)};
        *(uint4*)&g_pw[row*CC + c] = r;
        return;
    }
    const float* W = (wi == 0) ? cq : (wi == 1) ? ck : cv;
    const float* M = (wi == 0) ? qm : (wi == 1) ? km : vm;
    float* O       = (wi == 0) ? g_qw : (wi == 1) ? g_kw : g_vw;
    int h = row >> 6, d = row & 63;
    float mx[16];
#pragma unroll
    for (int m = 0; m < 16; m++) mx[m] = M[h*16 + m];
    int c = threadIdx.x * 4;
    float4 s = {0.f, 0.f, 0.f, 0.f};
#pragma unroll
    for (int m = 0; m < 16; m++) {
        float4 w = *(const float4*)&W[(size_t)(m*64 + d)*CC + c];
        s.x += mx[m]*w.x; s.y += mx[m]*w.y;
        s.z += mx[m]*w.z; s.w += mx[m]*w.w;
    }
    uint4 r = {f2tf32(s.x), f2tf32(s.y), f2tf32(s.z), f2tf32(s.w)};
    *(uint4*)&O[row*CC + c] = r;
}

// ---------------- 2) NT GEMM, tf32 mma, BK=32, 2-stage cp.async -------------
// A and B already tf32-rounded fp32. smem [m][36] (stride 36: conflict-free
// fragments, 144B rows keep 16B cp.async alignment). Block 128x128.
#define GST 36
#define GEMM_SMEM (2*2*128*GST*4)   // 73728 B

__global__ __launch_bounds__(256, 2) void gemm_tf32_kernel(
    const float* __restrict__ A,
    const float* __restrict__ B0, float* __restrict__ C0,
    const float* __restrict__ B1, float* __restrict__ C1,
    const float* __restrict__ B2, float* __restrict__ C2,
    int K) {
    const float* Bm = (blockIdx.z == 0) ? B0 : (blockIdx.z == 1) ? B1 : B2;
    float*       Cm = (blockIdx.z == 0) ? C0 : (blockIdx.z == 1) ? C1 : C2;
    const int N = CC;

    extern __shared__ float gsm[];
    float* Asm = gsm;                 // [2][128][36]
    float* Bsm = gsm + 2*128*GST;     // [2][128][36]

    const int tid  = threadIdx.x;
    const int lane = tid & 31;
    const int warp = tid >> 5;
    const int wr = warp & 1;          // 64-row strip
    const int wc = warp >> 1;         // 32-col strip
    const int g  = lane >> 2;
    const int l4 = lane & 3;
    const int brow = blockIdx.x * 128, bcol = blockIdx.y * 128;

    // loader: row = tid>>1, k-half = (tid&1)*16, four 16B chunks
    const int lrow  = tid >> 1;
    const int lhalf = (tid & 1) * 16;
    const float* Ab = A  + (size_t)(brow + lrow) * K + lhalf;
    const float* Bb = Bm + (size_t)(bcol + lrow) * K + lhalf;
    const uint32_t Ad = (uint32_t)__cvta_generic_to_shared(Asm + lrow*GST + lhalf);
    const uint32_t Bd = (uint32_t)__cvta_generic_to_shared(Bsm + lrow*GST + lhalf);
    const uint32_t stageB = 128*GST*4;

    const int NIT = K / 32;   // 32

    // prologue: stage 0
#pragma unroll
    for (int c = 0; c < 4; c++) {
        cp_async16(Ad + c*16, Ab + c*4);
        cp_async16(Bd + c*16, Bb + c*4);
    }
    cp_commit();

    float acc[4][4][4];
#pragma unroll
    for (int mi = 0; mi < 4; mi++)
#pragma unroll
        for (int ni = 0; ni < 4; ni++)
#pragma unroll
            for (int r = 0; r < 4; r++) acc[mi][ni][r] = 0.f;

    for (int it = 0; it < NIT; it++) {
        cp_wait0();
        __syncthreads();
        // prefetch stage it+1 (lands during this iteration's 64 mmas)
        if (it + 1 < NIT) {
            uint32_t so = ((it + 1) & 1) * stageB;
            int go = (it + 1) * 32;
#pragma unroll
            for (int c = 0; c < 4; c++) {
                cp_async16(Ad + so + c*16, Ab + go + c*4);
                cp_async16(Bd + so + c*16, Bb + go + c*4);
            }
            cp_commit();
        }
        const float* Ap = Asm + (it & 1)*128*GST;
        const float* Bp = Bsm + (it & 1)*128*GST;
#pragma unroll
        for (int ks = 0; ks < 4; ks++) {
            const int k0 = ks*8;
            uint32_t bf[4][2];
#pragma unroll
            for (int ni = 0; ni < 4; ni++) {
                const float* bp = Bp + (wc*32 + ni*8 + g)*GST + k0 + l4;
                bf[ni][0] = __float_as_uint(bp[0]);
                bf[ni][1] = __float_as_uint(bp[4]);
            }
#pragma unroll
            for (int mi = 0; mi < 4; mi++) {
                const float* ap0 = Ap + (wr*64 + mi*16 + g)*GST + k0 + l4;
                const float* ap1 = ap0 + 8*GST;
                uint32_t a0 = __float_as_uint(ap0[0]);
                uint32_t a1 = __float_as_uint(ap1[0]);
                uint32_t a2 = __float_as_uint(ap0[4]);
                uint32_t a3 = __float_as_uint(ap1[4]);
#pragma unroll
                for (int ni = 0; ni < 4; ni++)
                    mma_tf32(acc[mi][ni], a0, a1, a2, a3, bf[ni][0], bf[ni][1]);
            }
        }
    }

#pragma unroll
    for (int mi = 0; mi < 4; mi++) {
#pragma unroll
        for (int ni = 0; ni < 4; ni++) {
            int row0 = brow + wr*64 + mi*16 + g;
            int col  = bcol + wc*32 + ni*8 + 2*l4;
            float2 w0 = {acc[mi][ni][0], acc[mi][ni][1]};
            float2 w1 = {acc[mi][ni][2], acc[mi][ni][3]};
            *(float2*)(Cm + (size_t)row0 * N + col)       = w0;
            *(float2*)(Cm + (size_t)(row0 + 8) * N + col) = w1;
        }
    }
}

// ---------------- 3) gates + RoPE + RMSNorm; q/k/v pre-rounded to tf32 ------
__global__ void post_kernel(const float* __restrict__ x, const float* __restrict__ ve,
                            const float* __restrict__ cosb, const float* __restrict__ sinb,
                            const float* __restrict__ vgw, const float* __restrict__ agw) {
    int gw   = (blockIdx.x * blockDim.x + threadIdx.x) >> 5;
    int lane = threadIdx.x & 31;
    if (gw >= NROWS*HH) return;
    int h  = gw % HH;
    int bt = gw / HH;
    int t  = bt % TT;
    size_t xbase = (size_t)bt * CC;

    float gv = x[xbase + lane] * vgw[h*32 + lane];
#pragma unroll
    for (int o = 16; o > 0; o >>= 1) gv += __shfl_xor_sync(0xffffffffu, gv, o);
    float gate_v = 2.f / (1.f + __expf(-gv));

    float ga = (lane < 12) ? x[xbase + lane] * agw[h*12 + lane] : 0.f;
#pragma unroll
    for (int o = 16; o > 0; o >>= 1) ga += __shfl_xor_sync(0xffffffffu, ga, o);
    if (lane == 0) g_ga[(size_t)bt*HH + h] = 1.f / (1.f + __expf(-ga));

    size_t idx = xbase + h*64;
    float v1 = g_v[idx + lane]      + gate_v * ve[idx + lane];
    float v2 = g_v[idx + lane + 32] + gate_v * ve[idx + lane + 32];
    g_v[idx + lane]      = __uint_as_float(f2tf32(v1));
    g_v[idx + lane + 32] = __uint_as_float(f2tf32(v2));

    float cs = cosb[t*32 + lane], sn = sinb[t*32 + lane];
    {
        float q1 = g_q[idx + lane], q2 = g_q[idx + lane + 32];
        float r1 =  q1*cs + q2*sn;
        float r2 = -q1*sn + q2*cs;
        float ss = r1*r1 + r2*r2;
#pragma unroll
        for (int o = 16; o > 0; o >>= 1) ss += __shfl_xor_sync(0xffffffffu, ss, o);
        float sc = rsqrtf(ss * (1.f/64.f) + 1e-6f);
        g_q[idx + lane]      = __uint_as_float(f2tf32(r1*sc));
        g_q[idx + lane + 32] = __uint_as_float(f2tf32(r2*sc));
    }
    {
        float k1 = g_k[idx + lane], k2 = g_k[idx + lane + 32];
        float r1 =  k1*cs + k2*sn;
        float r2 = -k1*sn + k2*cs;
        float ss = r1*r1 + r2*r2;
#pragma unroll
        for (int o = 16; o > 0; o >>= 1) ss += __shfl_xor_sync(0xffffffffu, ss, o);
        float sc = rsqrtf(ss * (1.f/64.f) + 1e-6f);
        g_k[idx + lane]      = __uint_as_float(f2tf32(r1*sc));
        g_k[idx + lane + 32] = __uint_as_float(f2tf32(r2*sc));
    }
}

// ---------------- 4) flash attention via tf32 mma, BM=128, BN=64 ------------
#define AST 68
#define ATTN_SMEM ((128*AST + 4*64*AST)*4)

__global__ __launch_bounds__(256, 2) void attn_kernel(const int* __restrict__ wsp) {
    extern __shared__ float smf[];
    float* QPs = smf;                       // [128][AST]
    float* Ks  = smf + 128*AST;             // [2][64][AST]
    float* Vs  = Ks  + 2*64*AST;            // [2][64][AST]
    uint32_t* QPu = (uint32_t*)QPs;

    const int qtb = (TT/128 - 1) - blockIdx.x;
    const int h = blockIdx.y, b = blockIdx.z;
    const int tid  = threadIdx.x;
    const int lane = tid & 31;
    const int w    = tid >> 5;
    const int g    = lane >> 2;
    const int l4   = lane & 3;
    const int q0   = qtb * 128;
    const int hoff = h*64;
    const size_t bT = (size_t)b*TT;

    int wsv = wsp ? *wsp : -1;
    const bool use_w = (wsv >= 0) && (wsv < TT - 1);
    int jt0 = 0;
    if (use_w) {
        int lo = q0 - wsv - 63;
        if (lo > 0) jt0 = (lo + 63) >> 6;
    }
    const int jtmax = 2*qtb + 1;

    {
        int row = tid >> 1;
        int c0  = (tid & 1) * 8;
        const float* src = g_q + (bT + q0 + row)*CC + hoff;
        uint32_t dst = (uint32_t)__cvta_generic_to_shared(QPs + row*AST);
#pragma unroll
        for (int i = 0; i < 8; i++) cp_async16(dst + (c0 + i)*16, src + (c0 + i)*4);
        cp_commit();
    }
    {
        int r  = tid >> 2;
        int c0 = (tid & 3) * 4;
        int pos = jt0*64 + r;
        int sh  = (pos > 0) ? pos - 1 : 0;
        uint32_t kd = (uint32_t)__cvta_generic_to_shared(Ks + (jt0&1)*64*AST + r*AST);
        uint32_t vd = (uint32_t)__cvta_generic_to_shared(Vs + (jt0&1)*64*AST + r*AST);
        const float* kp = g_k + (bT + pos)*CC + hoff;
        const float* ks = g_k + (bT + sh)*CC + hoff;
        const float* vp = g_v + (bT + pos)*CC + hoff;
#pragma unroll
        for (int i = 0; i < 4; i++) {
            int c = c0 + i;
            const float* kb = (c < 8) ? kp : ks;
            cp_async16(kd + c*16, kb + c*4);
            cp_async16(vd + c*16, vp + c*4);
        }
        cp_commit();
    }

    uint32_t qa[8][4];
    cp_wait1();
    __syncthreads();
    {
        const float* q0p = QPs + (16*w + g)*AST;
        const float* q1p = QPs + (16*w + g + 8)*AST;
#pragma unroll
        for (int ks = 0; ks < 8; ks++) {
            qa[ks][0] = __float_as_uint(q0p[8*ks + l4]);
            qa[ks][1] = __float_as_uint(q1p[8*ks + l4]);
            qa[ks][2] = __float_as_uint(q0p[8*ks + l4 + 4]);
            qa[ks][3] = __float_as_uint(q1p[8*ks + l4 + 4]);
        }
    }
    __syncwarp();

    float oacc[8][4];
#pragma unroll
    for (int nt = 0; nt < 8; nt++)
#pragma unroll
        for (int r = 0; r < 4; r++) oacc[nt][r] = 0.f;
    float mi0 = -1e30f, mi1 = -1e30f, li0 = 0.f, li1 = 0.f;

    const int wrmin = q0 + 16*w;
    const int wrmax = wrmin + 15;
    const int r0g   = wrmin + g;
    const int r1g   = r0g + 8;
    uint32_t* Pw0 = QPu + (16*w + g)*AST;
    uint32_t* Pw1 = QPu + (16*w + g + 8)*AST;

    for (int jt = jt0; jt <= jtmax; jt++) {
        const int kv0 = jt * 64;
        const int buf = jt & 1;
        cp_wait0();
        __syncthreads();

        if (jt < jtmax) {
            int r  = tid >> 2;
            int c0 = (tid & 3) * 4;
            int pos = kv0 + 64 + r;
            uint32_t kd = (uint32_t)__cvta_generic_to_shared(Ks + (buf^1)*64*AST + r*AST);
            uint32_t vd = (uint32_t)__cvta_generic_to_shared(Vs + (buf^1)*64*AST + r*AST);
            const float* kp = g_k + (bT + pos)*CC + hoff;
            const float* ksh = g_k + (bT + pos - 1)*CC + hoff;
            const float* vp = g_v + (bT + pos)*CC + hoff;
#pragma unroll
            for (int i = 0; i < 4; i++) {
                int c = c0 + i;
                const float* kb = (c < 8) ? kp : ksh;
                cp_async16(kd + c*16, kb + c*4);
                cp_async16(vd + c*16, vp + c*4);
            }
            cp_commit();
        }

        bool dead = (kv0 > wrmax) || (use_w && (kv0 + 63 < wrmin - wsv));
        if (!dead) {
            const float* Kb = Ks + buf*64*AST;
            const float* Vb = Vs + buf*64*AST;

            float sacc[8][4];
#pragma unroll
            for (int nt = 0; nt < 8; nt++)
#pragma unroll
                for (int r = 0; r < 4; r++) sacc[nt][r] = 0.f;
#pragma unroll
            for (int ks = 0; ks < 8; ks++) {
#pragma unroll
                for (int nt = 0; nt < 8; nt++) {
                    uint32_t b0 = __float_as_uint(Kb[(8*nt + g)*AST + 8*ks + l4]);
                    uint32_t b1 = __float_as_uint(Kb[(8*nt + g)*AST + 8*ks + l4 + 4]);
                    mma_tf32(sacc[nt], qa[ks][0], qa[ks][1], qa[ks][2], qa[ks][3], b0, b1);
                }
            }

            const bool full = (kv0 + 63 <= wrmin) &&
                              (!use_w || (wrmax - kv0 <= wsv));
            if (full) {
#pragma unroll
                for (int nt = 0; nt < 8; nt++)
#pragma unroll
                    for (int r = 0; r < 4; r++) sacc[nt][r] *= 0.125f;
            } else {
#pragma unroll
                for (int nt = 0; nt < 8; nt++) {
                    int c0 = kv0 + 8*nt + 2*l4;
#pragma unroll
                    for (int r = 0; r < 4; r++) {
                        int qi = (r < 2) ? r0g : r1g;
                        int kj = c0 + (r & 1);
                        bool ok = (kj <= qi) && (!use_w || (qi - kj) <= wsv);
                        sacc[nt][r] = ok ? sacc[nt][r]*0.125f : -1e30f;
                    }
                }
            }

            float mx0 = -1e30f, mx1 = -1e30f;
#pragma unroll
            for (int nt = 0; nt < 8; nt++) {
                mx0 = fmaxf(mx0, fmaxf(sacc[nt][0], sacc[nt][1]));
                mx1 = fmaxf(mx1, fmaxf(sacc[nt][2], sacc[nt][3]));
            }
            mx0 = fmaxf(mx0, __shfl_xor_sync(0xffffffffu, mx0, 1));
            mx0 = fmaxf(mx0, __shfl_xor_sync(0xffffffffu, mx0, 2));
            mx1 = fmaxf(mx1, __shfl_xor_sync(0xffffffffu, mx1, 1));
            mx1 = fmaxf(mx1, __shfl_xor_sync(0xffffffffu, mx1, 2));
            float mn0 = fmaxf(fmaxf(mi0, mx0), -1e29f);
            float mn1 = fmaxf(fmaxf(mi1, mx1), -1e29f);
            float corr0 = __expf(mi0 - mn0);
            float corr1 = __expf(mi1 - mn1);
            float sum0 = 0.f, sum1 = 0.f;
#pragma unroll
            for (int nt = 0; nt < 8; nt++) {
                float p0 = __expf(sacc[nt][0] - mn0);
                float p1 = __expf(sacc[nt][1] - mn0);
                float p2 = __expf(sacc[nt][2] - mn1);
                float p3 = __expf(sacc[nt][3] - mn1);
                sum0 += p0 + p1; sum1 += p2 + p3;
                uint2 w0 = {f2tf32(p0), f2tf32(p1)};
                uint2 w1 = {f2tf32(p2), f2tf32(p3)};
                *(uint2*)(Pw0 + 8*nt + 2*l4) = w0;
                *(uint2*)(Pw1 + 8*nt + 2*l4) = w1;
            }
            sum0 += __shfl_xor_sync(0xffffffffu, sum0, 1);
            sum0 += __shfl_xor_sync(0xffffffffu, sum0, 2);
            sum1 += __shfl_xor_sync(0xffffffffu, sum1, 1);
            sum1 += __shfl_xor_sync(0xffffffffu, sum1, 2);
            li0 = li0*corr0 + sum0;
            li1 = li1*corr1 + sum1;
            mi0 = mn0; mi1 = mn1;
#pragma unroll
            for (int nt = 0; nt < 8; nt++) {
                oacc[nt][0] *= corr0; oacc[nt][1] *= corr0;
                oacc[nt][2] *= corr1; oacc[nt][3] *= corr1;
            }
            __syncwarp();

#pragma unroll
            for (int ks = 0; ks < 8; ks++) {
                uint32_t a0 = Pw0[8*ks + l4];
                uint32_t a1 = Pw1[8*ks + l4];
                uint32_t a2 = Pw0[8*ks + l4 + 4];
                uint32_t a3 = Pw1[8*ks + l4 + 4];
#pragma unroll
                for (int nt = 0; nt < 8; nt++) {
                    uint32_t b0 = __float_as_uint(Vb[(8*ks + l4)*AST + 8*nt + g]);
                    uint32_t b1 = __float_as_uint(Vb[(8*ks + l4 + 4)*AST + 8*nt + g]);
                    mma_tf32(oacc[nt], a0, a1, a2, a3, b0, b1);
                }
            }
            __syncwarp();
        }
    }

    float ga0 = g_ga[(bT + r0g)*HH + h];
    float ga1 = g_ga[(bT + r1g)*HH + h];
    float inv0 = ga0 / li0;
    float inv1 = ga1 / li1;
    float* y0 = g_y + (bT + r0g)*CC + hoff;
    float* y1 = g_y + (bT + r1g)*CC + hoff;
#pragma unroll
    for (int nt = 0; nt < 8; nt++) {
        int c = 8*nt + 2*l4;
        uint2 w0 = {f2tf32(oacc[nt][0]*inv0), f2tf32(oacc[nt][1]*inv0)};
        uint2 w1 = {f2tf32(oacc[nt][2]*inv1), f2tf32(oacc[nt][3]*inv1)};
        *(uint2*)(y0 + c) = w0;
        *(uint2*)(y1 + c) = w1;
    }
}

// ---------------- launch ----------------------------------------------------
extern "C" void kernel_launch(void* const* d_in, const int* in_sizes, int n_in,
                              void* d_out, int out_size) {
    const float* x    = (const float*)d_in[0];
    const float* ve   = (const float*)d_in[1];
    const float* cosb = (const float*)d_in[2];
    const float* sinb = (const float*)d_in[3];
    const float* cqw  = (const float*)d_in[4];
    const float* ckw  = (const float*)d_in[5];
    const float* cvw  = (const float*)d_in[6];
    const float* cpw  = (const float*)d_in[7];
    const float* vgw  = (const float*)d_in[8];
    const float* agw  = (const float*)d_in[9];
    const float* qm   = (const float*)d_in[10];
    const float* km   = (const float*)d_in[11];
    const float* vm   = (const float*)d_in[12];
    const int*   wsp  = (n_in > 13) ? (const int*)d_in[13] : nullptr;
    float* out = (float*)d_out;

    float *pqw, *pkw, *pvw, *ppw, *pxt, *pq, *pk, *pv, *py;
    cudaGetSymbolAddress((void**)&pqw, g_qw);
    cudaGetSymbolAddress((void**)&pkw, g_kw);
    cudaGetSymbolAddress((void**)&pvw, g_vw);
    cudaGetSymbolAddress((void**)&ppw, g_pw);
    cudaGetSymbolAddress((void**)&pxt, g_xt);
    cudaGetSymbolAddress((void**)&pq,  g_q);
    cudaGetSymbolAddress((void**)&pk,  g_k);
    cudaGetSymbolAddress((void**)&pv,  g_v);
    cudaGetSymbolAddress((void**)&py,  g_y);

    // 0) round x to tf32
    round_x_kernel<<<NROWS*CC/1024, 256>>>(x);

    // 1) fuse mixes into weights (rounded) + round cpw
    fuse_kernel<<<dim3(CC, 4), 256>>>(cqw, ckw, cvw, cpw, qm, km, vm);

    // 2) QKV projections
    cudaFuncSetAttribute(gemm_tf32_kernel, cudaFuncAttributeMaxDynamicSharedMemorySize, GEMM_SMEM);
    gemm_tf32_kernel<<<dim3(NROWS/128, CC/128, 3), 256, GEMM_SMEM>>>(
        pxt, pqw, pq, pkw, pk, pvw, pv, CC);

    // 3) gates + rope + rmsnorm (+ tf32 rounding)
    post_kernel<<<(NROWS*HH*32)/256, 256>>>(x, ve, cosb, sinb, vgw, agw);

    // 4) flash attention (tf32 tensor cores)
    cudaFuncSetAttribute(attn_kernel, cudaFuncAttributeMaxDynamicSharedMemorySize, ATTN_SMEM);
    attn_kernel<<<dim3(TT/128, HH, BB), 256, ATTN_SMEM>>>(wsp);

    // 5) output projection
    gemm_tf32_kernel<<<dim3(NROWS/128, CC/128, 1), 256, GEMM_SMEM>>>(
        py, ppw, out, ppw, out, ppw, out, CC);
}

// round 11
// speedup vs baseline: 1.3778x; 1.3778x over previous
#include <cuda_runtime.h>
#include <cuda_fp16.h>
#include <cstdint>
#include <cstddef>
#include <math.h>

#define BB 2
#define TT 2048
#define CC 1024
#define HH 16
#define NROWS (BB*TT)   // 4096

// ---------------- scratch (static device allocations; no cudaMalloc) -------
__device__ __half g_qwh[CC*CC];
__device__ __half g_kwh[CC*CC];
__device__ __half g_vwh[CC*CC];
__device__ __half g_pwh[CC*CC];
__device__ __half g_xh[NROWS*CC];
__device__ __half g_yh[NROWS*CC];
__device__ float  g_q[NROWS*CC];
__device__ float  g_k[NROWS*CC];
__device__ float  g_v[NROWS*CC];
__device__ float  g_ga[NROWS*HH];

// ---------------- helpers ----------------------------------------------------
__device__ __forceinline__ void cp_async16(uint32_t saddr, const void* g) {
    asm volatile("cp.async.cg.shared.global [%0], [%1], 16;\n" :: "r"(saddr), "l"(g));
}
__device__ __forceinline__ void cp_commit() {
    asm volatile("cp.async.commit_group;\n");
}
__device__ __forceinline__ void cp_wait0() {
    asm volatile("cp.async.wait_group 0;\n");
}
__device__ __forceinline__ void cp_wait1() {
    asm volatile("cp.async.wait_group 1;\n");
}
__device__ __forceinline__ uint32_t f2tf32(float x) {
    uint32_t r;
    asm("cvt.rna.tf32.f32 %0, %1;" : "=r"(r) : "f"(x));
    return r;
}
__device__ __forceinline__ void mma_tf32(float c[4], uint32_t a0, uint32_t a1,
                                         uint32_t a2, uint32_t a3,
                                         uint32_t b0, uint32_t b1) {
    asm volatile(
        "mma.sync.aligned.m16n8k8.row.col.f32.tf32.tf32.f32 "
        "{%0,%1,%2,%3}, {%4,%5,%6,%7}, {%8,%9}, {%0,%1,%2,%3};"
        : "+f"(c[0]), "+f"(c[1]), "+f"(c[2]), "+f"(c[3])
        : "r"(a0), "r"(a1), "r"(a2), "r"(a3), "r"(b0), "r"(b1));
}
__device__ __forceinline__ void mma_fp16(float c[4], uint32_t a0, uint32_t a1,
                                         uint32_t a2, uint32_t a3,
                                         uint32_t b0, uint32_t b1) {
    asm volatile(
        "mma.sync.aligned.m16n8k16.row.col.f32.f16.f16.f32 "
        "{%0,%1,%2,%3}, {%4,%5,%6,%7}, {%8,%9}, {%0,%1,%2,%3};"
        : "+f"(c[0]), "+f"(c[1]), "+f"(c[2]), "+f"(c[3])
        : "r"(a0), "r"(a1), "r"(a2), "r"(a3), "r"(b0), "r"(b1));
}

// ---------------- 0) round/convert x to fp16 ---------------------------------
__global__ void round_x_kernel(const float* __restrict__ x) {
    int i = blockIdx.x * blockDim.x + threadIdx.x;
    float4 v = ((const float4*)x)[i];
    __half2 h0 = __floats2half2_rn(v.x, v.y);
    __half2 h1 = __floats2half2_rn(v.z, v.w);
    uint2 r = {*(uint32_t*)&h0, *(uint32_t*)&h1};
    ((uint2*)g_xh)[i] = r;
}

// ---------------- 1) fuse mix into weights -> fp16; wi=3 converts cpw -------
__global__ void fuse_kernel(const float* __restrict__ cq, const float* __restrict__ ck,
                            const float* __restrict__ cv, const float* __restrict__ cp,
                            const float* __restrict__ qm,
                            const float* __restrict__ km, const float* __restrict__ vm) {
    int row = blockIdx.x;
    int wi  = blockIdx.y;
    int c = threadIdx.x * 4;
    if (wi == 3) {
        float4 v = *(const float4*)&cp[row*CC + c];
        __half2 h0 = __floats2half2_rn(v.x, v.y);
        __half2 h1 = __floats2half2_rn(v.z, v.w);
        uint2 r = {*(uint32_t*)&h0, *(uint32_t*)&h1};
        *(uint2*)&g_pwh[row*CC + c] = r;
        return;
    }
    const float* W = (wi == 0) ? cq : (wi == 1) ? ck : cv;
    const float* M = (wi == 0) ? qm : (wi == 1) ? km : vm;
    __half* O      = (wi == 0) ? g_qwh : (wi == 1) ? g_kwh : g_vwh;
    int h = row >> 6, d = row & 63;
    float mx[16];
#pragma unroll
    for (int m = 0; m < 16; m++) mx[m] = M[h*16 + m];
    float4 s = {0.f, 0.f, 0.f, 0.f};
#pragma unroll
    for (int m = 0; m < 16; m++) {
        float4 w = *(const float4*)&W[(size_t)(m*64 + d)*CC + c];
        s.x += mx[m]*w.x; s.y += mx[m]*w.y;
        s.z += mx[m]*w.z; s.w += mx[m]*w.w;
    }
    __half2 h0 = __floats2half2_rn(s.x, s.y);
    __half2 h1 = __floats2half2_rn(s.z, s.w);
    uint2 r = {*(uint32_t*)&h0, *(uint32_t*)&h1};
    *(uint2*)&O[row*CC + c] = r;
}

// ---------------- 2) NT GEMM, fp16 m16n8k16, BK=32, 3-stage cp.async --------
// smem rows: 64B data + 16B pad (stride 80B = 20 words). Fragment word bank =
// (20g + l4) % 32 -> all 32 lanes distinct, conflict-free.
#define HST 40                       // halves per smem row
#define HSTG (128*HST)               // halves per stage per matrix
#define GEMM_SMEM (3*2*HSTG*2)       // 61440 bytes

__global__ __launch_bounds__(256, 2) void gemm_fp16_kernel(
    const __half* __restrict__ A,
    const __half* __restrict__ B0, float* __restrict__ C0,
    const __half* __restrict__ B1, float* __restrict__ C1,
    const __half* __restrict__ B2, float* __restrict__ C2,
    int K) {
    const __half* Bm = (blockIdx.z == 0) ? B0 : (blockIdx.z == 1) ? B1 : B2;
    float*        Cm = (blockIdx.z == 0) ? C0 : (blockIdx.z == 1) ? C1 : C2;
    const int N = CC;

    extern __shared__ __half hsm[];
    __half* Asm = hsm;                 // [3][128][HST]
    __half* Bsm = hsm + 3*HSTG;        // [3][128][HST]

    const int tid  = threadIdx.x;
    const int lane = tid & 31;
    const int warp = tid >> 5;
    const int wr = warp & 1;           // 64-row strip
    const int wc = warp >> 1;          // 32-col strip
    const int g  = lane >> 2;
    const int l4 = lane & 3;
    const int brow = blockIdx.x * 128, bcol = blockIdx.y * 128;

    // loader: row = tid>>1, two 16B chunks at byte (tid&1)*32 + {0,16}
    const int lrow = tid >> 1;
    const int lch  = (tid & 1) * 16;   // half offset within row: 0 or 16
    const __half* Ab = A  + (size_t)(brow + lrow) * K + lch;
    const __half* Bb = Bm + (size_t)(bcol + lrow) * K + lch;
    const uint32_t Ad = (uint32_t)__cvta_generic_to_shared(Asm + lrow*HST + lch);
    const uint32_t Bd = (uint32_t)__cvta_generic_to_shared(Bsm + lrow*HST + lch);
    const uint32_t stageB = HSTG * 2;  // bytes per stage per matrix

    const int NIT = K / 32;            // 32

    // prologue: stages 0, 1
#pragma unroll
    for (int s = 0; s < 2; s++) {
        cp_async16(Ad + s*stageB,      Ab + s*32);
        cp_async16(Ad + s*stageB + 16, Ab + s*32 + 8);
        cp_async16(Bd + s*stageB,      Bb + s*32);
        cp_async16(Bd + s*stageB + 16, Bb + s*32 + 8);
        cp_commit();
    }

    float acc[4][4][4];
#pragma unroll
    for (int mi = 0; mi < 4; mi++)
#pragma unroll
        for (int ni = 0; ni < 4; ni++)
#pragma unroll
            for (int r = 0; r < 4; r++) acc[mi][ni][r] = 0.f;

    for (int it = 0; it < NIT; it++) {
        if (it + 1 < NIT) cp_wait1(); else cp_wait0();
        __syncthreads();
        // prefetch stage it+2
        if (it + 2 < NIT) {
            int s = (it + 2) % 3;
            cp_async16(Ad + s*stageB,      Ab + (it+2)*32);
            cp_async16(Ad + s*stageB + 16, Ab + (it+2)*32 + 8);
            cp_async16(Bd + s*stageB,      Bb + (it+2)*32);
            cp_async16(Bd + s*stageB + 16, Bb + (it+2)*32 + 8);
            cp_commit();
        }
        const uint32_t* Aw = (const uint32_t*)(Asm + (it % 3)*HSTG);
        const uint32_t* Bw = (const uint32_t*)(Bsm + (it % 3)*HSTG);
#pragma unroll
        for (int ks = 0; ks < 2; ks++) {
            const int k0w = ks*8;
            uint32_t bf[4][2];
#pragma unroll
            for (int ni = 0; ni < 4; ni++) {
                const uint32_t* bp = Bw + (wc*32 + ni*8 + g)*20 + k0w + l4;
                bf[ni][0] = bp[0];
                bf[ni][1] = bp[4];
            }
#pragma unroll
            for (int mi = 0; mi < 4; mi++) {
                const uint32_t* ap0 = Aw + (wr*64 + mi*16 + g)*20 + k0w + l4;
                const uint32_t* ap1 = ap0 + 8*20;
                uint32_t a0 = ap0[0];
                uint32_t a1 = ap1[0];
                uint32_t a2 = ap0[4];
                uint32_t a3 = ap1[4];
#pragma unroll
                for (int ni = 0; ni < 4; ni++)
                    mma_fp16(acc[mi][ni], a0, a1, a2, a3, bf[ni][0], bf[ni][1]);
            }
        }
    }

#pragma unroll
    for (int mi = 0; mi < 4; mi++) {
#pragma unroll
        for (int ni = 0; ni < 4; ni++) {
            int row0 = brow + wr*64 + mi*16 + g;
            int col  = bcol + wc*32 + ni*8 + 2*l4;
            float2 w0 = {acc[mi][ni][0], acc[mi][ni][1]};
            float2 w1 = {acc[mi][ni][2], acc[mi][ni][3]};
            *(float2*)(Cm + (size_t)row0 * N + col)       = w0;
            *(float2*)(Cm + (size_t)(row0 + 8) * N + col) = w1;
        }
    }
}

// ---------------- 3) gates + RoPE + RMSNorm; q/k/v rounded to tf32 ----------
__global__ void post_kernel(const float* __restrict__ x, const float* __restrict__ ve,
                            const float* __restrict__ cosb, const float* __restrict__ sinb,
                            const float* __restrict__ vgw, const float* __restrict__ agw) {
    int gw   = (blockIdx.x * blockDim.x + threadIdx.x) >> 5;
    int lane = threadIdx.x & 31;
    if (gw >= NROWS*HH) return;
    int h  = gw % HH;
    int bt = gw / HH;
    int t  = bt % TT;
    size_t xbase = (size_t)bt * CC;

    float gv = x[xbase + lane] * vgw[h*32 + lane];
#pragma unroll
    for (int o = 16; o > 0; o >>= 1) gv += __shfl_xor_sync(0xffffffffu, gv, o);
    float gate_v = 2.f / (1.f + __expf(-gv));

    float ga = (lane < 12) ? x[xbase + lane] * agw[h*12 + lane] : 0.f;
#pragma unroll
    for (int o = 16; o > 0; o >>= 1) ga += __shfl_xor_sync(0xffffffffu, ga, o);
    if (lane == 0) g_ga[(size_t)bt*HH + h] = 1.f / (1.f + __expf(-ga));

    size_t idx = xbase + h*64;
    float v1 = g_v[idx + lane]      + gate_v * ve[idx + lane];
    float v2 = g_v[idx + lane + 32] + gate_v * ve[idx + lane + 32];
    g_v[idx + lane]      = __uint_as_float(f2tf32(v1));
    g_v[idx + lane + 32] = __uint_as_float(f2tf32(v2));

    float cs = cosb[t*32 + lane], sn = sinb[t*32 + lane];
    {
        float q1 = g_q[idx + lane], q2 = g_q[idx + lane + 32];
        float r1 =  q1*cs + q2*sn;
        float r2 = -q1*sn + q2*cs;
        float ss = r1*r1 + r2*r2;
#pragma unroll
        for (int o = 16; o > 0; o >>= 1) ss += __shfl_xor_sync(0xffffffffu, ss, o);
        float sc = rsqrtf(ss * (1.f/64.f) + 1e-6f);
        g_q[idx + lane]      = __uint_as_float(f2tf32(r1*sc));
        g_q[idx + lane + 32] = __uint_as_float(f2tf32(r2*sc));
    }
    {
        float k1 = g_k[idx + lane], k2 = g_k[idx + lane + 32];
        float r1 =  k1*cs + k2*sn;
        float r2 = -k1*sn + k2*cs;
        float ss = r1*r1 + r2*r2;
#pragma unroll
        for (int o = 16; o > 0; o >>= 1) ss += __shfl_xor_sync(0xffffffffu, ss, o);
        float sc = rsqrtf(ss * (1.f/64.f) + 1e-6f);
        g_k[idx + lane]      = __uint_as_float(f2tf32(r1*sc));
        g_k[idx + lane + 32] = __uint_as_float(f2tf32(r2*sc));
    }
}

// ---------------- 4) flash attention via tf32 mma, BM=128, BN=64 ------------
#define AST 68
#define ATTN_SMEM ((128*AST + 4*64*AST)*4)

__global__ __launch_bounds__(256, 2) void attn_kernel(const int* __restrict__ wsp) {
    extern __shared__ float smf[];
    float* QPs = smf;                       // [128][AST]
    float* Ks  = smf + 128*AST;             // [2][64][AST]
    float* Vs  = Ks  + 2*64*AST;            // [2][64][AST]
    uint32_t* QPu = (uint32_t*)QPs;

    const int qtb = (TT/128 - 1) - blockIdx.x;
    const int h = blockIdx.y, b = blockIdx.z;
    const int tid  = threadIdx.x;
    const int lane = tid & 31;
    const int w    = tid >> 5;
    const int g    = lane >> 2;
    const int l4   = lane & 3;
    const int q0   = qtb * 128;
    const int hoff = h*64;
    const size_t bT = (size_t)b*TT;

    int wsv = wsp ? *wsp : -1;
    const bool use_w = (wsv >= 0) && (wsv < TT - 1);
    int jt0 = 0;
    if (use_w) {
        int lo = q0 - wsv - 63;
        if (lo > 0) jt0 = (lo + 63) >> 6;
    }
    const int jtmax = 2*qtb + 1;

    {
        int row = tid >> 1;
        int c0  = (tid & 1) * 8;
        const float* src = g_q + (bT + q0 + row)*CC + hoff;
        uint32_t dst = (uint32_t)__cvta_generic_to_shared(QPs + row*AST);
#pragma unroll
        for (int i = 0; i < 8; i++) cp_async16(dst + (c0 + i)*16, src + (c0 + i)*4);
        cp_commit();
    }
    {
        int r  = tid >> 2;
        int c0 = (tid & 3) * 4;
        int pos = jt0*64 + r;
        int sh  = (pos > 0) ? pos - 1 : 0;
        uint32_t kd = (uint32_t)__cvta_generic_to_shared(Ks + (jt0&1)*64*AST + r*AST);
        uint32_t vd = (uint32_t)__cvta_generic_to_shared(Vs + (jt0&1)*64*AST + r*AST);
        const float* kp = g_k + (bT + pos)*CC + hoff;
        const float* ks = g_k + (bT + sh)*CC + hoff;
        const float* vp = g_v + (bT + pos)*CC + hoff;
#pragma unroll
        for (int i = 0; i < 4; i++) {
            int c = c0 + i;
            const float* kb = (c < 8) ? kp : ks;
            cp_async16(kd + c*16, kb + c*4);
            cp_async16(vd + c*16, vp + c*4);
        }
        cp_commit();
    }

    uint32_t qa[8][4];
    cp_wait1();
    __syncthreads();
    {
        const float* q0p = QPs + (16*w + g)*AST;
        const float* q1p = QPs + (16*w + g + 8)*AST;
#pragma unroll
        for (int ks = 0; ks < 8; ks++) {
            qa[ks][0] = __float_as_uint(q0p[8*ks + l4]);
            qa[ks][1] = __float_as_uint(q1p[8*ks + l4]);
            qa[ks][2] = __float_as_uint(q0p[8*ks + l4 + 4]);
            qa[ks][3] = __float_as_uint(q1p[8*ks + l4 + 4]);
        }
    }
    __syncwarp();

    float oacc[8][4];
#pragma unroll
    for (int nt = 0; nt < 8; nt++)
#pragma unroll
        for (int r = 0; r < 4; r++) oacc[nt][r] = 0.f;
    float mi0 = -1e30f, mi1 = -1e30f, li0 = 0.f, li1 = 0.f;

    const int wrmin = q0 + 16*w;
    const int wrmax = wrmin + 15;
    const int r0g   = wrmin + g;
    const int r1g   = r0g + 8;
    uint32_t* Pw0 = QPu + (16*w + g)*AST;
    uint32_t* Pw1 = QPu + (16*w + g + 8)*AST;

    for (int jt = jt0; jt <= jtmax; jt++) {
        const int kv0 = jt * 64;
        const int buf = jt & 1;
        cp_wait0();
        __syncthreads();

        if (jt < jtmax) {
            int r  = tid >> 2;
            int c0 = (tid & 3) * 4;
            int pos = kv0 + 64 + r;
            uint32_t kd = (uint32_t)__cvta_generic_to_shared(Ks + (buf^1)*64*AST + r*AST);
            uint32_t vd = (uint32_t)__cvta_generic_to_shared(Vs + (buf^1)*64*AST + r*AST);
            const float* kp = g_k + (bT + pos)*CC + hoff;
            const float* ksh = g_k + (bT + pos - 1)*CC + hoff;
            const float* vp = g_v + (bT + pos)*CC + hoff;
#pragma unroll
            for (int i = 0; i < 4; i++) {
                int c = c0 + i;
                const float* kb = (c < 8) ? kp : ksh;
                cp_async16(kd + c*16, kb + c*4);
                cp_async16(vd + c*16, vp + c*4);
            }
            cp_commit();
        }

        bool dead = (kv0 > wrmax) || (use_w && (kv0 + 63 < wrmin - wsv));
        if (!dead) {
            const float* Kb = Ks + buf*64*AST;
            const float* Vb = Vs + buf*64*AST;

            float sacc[8][4];
#pragma unroll
            for (int nt = 0; nt < 8; nt++)
#pragma unroll
                for (int r = 0; r < 4; r++) sacc[nt][r] = 0.f;
#pragma unroll
            for (int ks = 0; ks < 8; ks++) {
#pragma unroll
                for (int nt = 0; nt < 8; nt++) {
                    uint32_t b0 = __float_as_uint(Kb[(8*nt + g)*AST + 8*ks + l4]);
                    uint32_t b1 = __float_as_uint(Kb[(8*nt + g)*AST + 8*ks + l4 + 4]);
                    mma_tf32(sacc[nt], qa[ks][0], qa[ks][1], qa[ks][2], qa[ks][3], b0, b1);
                }
            }

            const bool full = (kv0 + 63 <= wrmin) &&
                              (!use_w || (wrmax - kv0 <= wsv));
            if (full) {
#pragma unroll
                for (int nt = 0; nt < 8; nt++)
#pragma unroll
                    for (int r = 0; r < 4; r++) sacc[nt][r] *= 0.125f;
            } else {
#pragma unroll
                for (int nt = 0; nt < 8; nt++) {
                    int c0 = kv0 + 8*nt + 2*l4;
#pragma unroll
                    for (int r = 0; r < 4; r++) {
                        int qi = (r < 2) ? r0g : r1g;
                        int kj = c0 + (r & 1);
                        bool ok = (kj <= qi) && (!use_w || (qi - kj) <= wsv);
                        sacc[nt][r] = ok ? sacc[nt][r]*0.125f : -1e30f;
                    }
                }
            }

            float mx0 = -1e30f, mx1 = -1e30f;
#pragma unroll
            for (int nt = 0; nt < 8; nt++) {
                mx0 = fmaxf(mx0, fmaxf(sacc[nt][0], sacc[nt][1]));
                mx1 = fmaxf(mx1, fmaxf(sacc[nt][2], sacc[nt][3]));
            }
            mx0 = fmaxf(mx0, __shfl_xor_sync(0xffffffffu, mx0, 1));
            mx0 = fmaxf(mx0, __shfl_xor_sync(0xffffffffu, mx0, 2));
            mx1 = fmaxf(mx1, __shfl_xor_sync(0xffffffffu, mx1, 1));
            mx1 = fmaxf(mx1, __shfl_xor_sync(0xffffffffu, mx1, 2));
            float mn0 = fmaxf(fmaxf(mi0, mx0), -1e29f);
            float mn1 = fmaxf(fmaxf(mi1, mx1), -1e29f);
            float corr0 = __expf(mi0 - mn0);
            float corr1 = __expf(mi1 - mn1);
            float sum0 = 0.f, sum1 = 0.f;
#pragma unroll
            for (int nt = 0; nt < 8; nt++) {
                float p0 = __expf(sacc[nt][0] - mn0);
                float p1 = __expf(sacc[nt][1] - mn0);
                float p2 = __expf(sacc[nt][2] - mn1);
                float p3 = __expf(sacc[nt][3] - mn1);
                sum0 += p0 + p1; sum1 += p2 + p3;
                uint2 w0 = {f2tf32(p0), f2tf32(p1)};
                uint2 w1 = {f2tf32(p2), f2tf32(p3)};
                *(uint2*)(Pw0 + 8*nt + 2*l4) = w0;
                *(uint2*)(Pw1 + 8*nt + 2*l4) = w1;
            }
            sum0 += __shfl_xor_sync(0xffffffffu, sum0, 1);
            sum0 += __shfl_xor_sync(0xffffffffu, sum0, 2);
            sum1 += __shfl_xor_sync(0xffffffffu, sum1, 1);
            sum1 += __shfl_xor_sync(0xffffffffu, sum1, 2);
            li0 = li0*corr0 + sum0;
            li1 = li1*corr1 + sum1;
            mi0 = mn0; mi1 = mn1;
#pragma unroll
            for (int nt = 0; nt < 8; nt++) {
                oacc[nt][0] *= corr0; oacc[nt][1] *= corr0;
                oacc[nt][2] *= corr1; oacc[nt][3] *= corr1;
            }
            __syncwarp();

#pragma unroll
            for (int ks = 0; ks < 8; ks++) {
                uint32_t a0 = Pw0[8*ks + l4];
                uint32_t a1 = Pw1[8*ks + l4];
                uint32_t a2 = Pw0[8*ks + l4 + 4];
                uint32_t a3 = Pw1[8*ks + l4 + 4];
#pragma unroll
                for (int nt = 0; nt < 8; nt++) {
                    uint32_t b0 = __float_as_uint(Vb[(8*ks + l4)*AST + 8*nt + g]);
                    uint32_t b1 = __float_as_uint(Vb[(8*ks + l4 + 4)*AST + 8*nt + g]);
                    mma_tf32(oacc[nt], a0, a1, a2, a3, b0, b1);
                }
            }
            __syncwarp();
        }
    }

    // epilogue: normalize, gate, write y as fp16 (for the proj GEMM)
    float ga0 = g_ga[(bT + r0g)*HH + h];
    float ga1 = g_ga[(bT + r1g)*HH + h];
    float inv0 = ga0 / li0;
    float inv1 = ga1 / li1;
    __half* y0 = g_yh + (bT + r0g)*CC + hoff;
    __half* y1 = g_yh + (bT + r1g)*CC + hoff;
#pragma unroll
    for (int nt = 0; nt < 8; nt++) {
        int c = 8*nt + 2*l4;
        __half2 w0 = __floats2half2_rn(oacc[nt][0]*inv0, oacc[nt][1]*inv0);
        __half2 w1 = __floats2half2_rn(oacc[nt][2]*inv1, oacc[nt][3]*inv1);
        *(__half2*)(y0 + c) = w0;
        *(__half2*)(y1 + c) = w1;
    }
}

// ---------------- launch ----------------------------------------------------
extern "C" void kernel_launch(void* const* d_in, const int* in_sizes, int n_in,
                              void* d_out, int out_size) {
    const float* x    = (const float*)d_in[0];
    const float* ve   = (const float*)d_in[1];
    const float* cosb = (const float*)d_in[2];
    const float* sinb = (const float*)d_in[3];
    const float* cqw  = (const float*)d_in[4];
    const float* ckw  = (const float*)d_in[5];
    const float* cvw  = (const float*)d_in[6];
    const float* cpw  = (const float*)d_in[7];
    const float* vgw  = (const float*)d_in[8];
    const float* agw  = (const float*)d_in[9];
    const float* qm   = (const float*)d_in[10];
    const float* km   = (const float*)d_in[11];
    const float* vm   = (const float*)d_in[12];
    const int*   wsp  = (n_in > 13) ? (const int*)d_in[13] : nullptr;
    float* out = (float*)d_out;

    __half *pqwh, *pkwh, *pvwh, *ppwh, *pxh, *pyh;
    float *pq, *pk, *pv;
    cudaGetSymbolAddress((void**)&pqwh, g_qwh);
    cudaGetSymbolAddress((void**)&pkwh, g_kwh);
    cudaGetSymbolAddress((void**)&pvwh, g_vwh);
    cudaGetSymbolAddress((void**)&ppwh, g_pwh);
    cudaGetSymbolAddress((void**)&pxh,  g_xh);
    cudaGetSymbolAddress((void**)&pyh,  g_yh);
    cudaGetSymbolAddress((void**)&pq,   g_q);
    cudaGetSymbolAddress((void**)&pk,   g_k);
    cudaGetSymbolAddress((void**)&pv,   g_v);

    // 0) convert x to fp16
    round_x_kernel<<<NROWS*CC/1024, 256>>>(x);

    // 1) fuse mixes into weights (fp16) + convert cpw
    fuse_kernel<<<dim3(CC, 4), 256>>>(cqw, ckw, cvw, cpw, qm, km, vm);

    // 2) QKV projections (fp16 mma)
    cudaFuncSetAttribute(gemm_fp16_kernel, cudaFuncAttributeMaxDynamicSharedMemorySize, GEMM_SMEM);
    gemm_fp16_kernel<<<dim3(NROWS/128, CC/128, 3), 256, GEMM_SMEM>>>(
        pxh, pqwh, pq, pkwh, pk, pvwh, pv, CC);

    // 3) gates + rope + rmsnorm (+ tf32 rounding for attention)
    post_kernel<<<(NROWS*HH*32)/256, 256>>>(x, ve, cosb, sinb, vgw, agw);

    // 4) flash attention (tf32 mma)
    cudaFuncSetAttribute(attn_kernel, cudaFuncAttributeMaxDynamicSharedMemorySize, ATTN_SMEM);
    attn_kernel<<<dim3(TT/128, HH, BB), 256, ATTN_SMEM>>>(wsp);

    // 5) output projection (fp16 mma)
    gemm_fp16_kernel<<<dim3(NROWS/128, CC/128, 1), 256, GEMM_SMEM>>>(
        pyh, ppwh, out, ppwh, out, ppwh, out, CC);
}

// round 13
// speedup vs baseline: 1.9925x; 1.4461x over previous
#include <cuda_runtime.h>
#include <cuda_fp16.h>
#include <cstdint>
#include <cstddef>
#include <math.h>

#define BB 2
#define TT 2048
#define CC 1024
#define HH 16
#define NROWS (BB*TT)   // 4096

// ---------------- scratch (static device allocations; no cudaMalloc) -------
__device__ __half g_qwh[CC*CC];
__device__ __half g_kwh[CC*CC];
__device__ __half g_vwh[CC*CC];
__device__ __half g_pwh[CC*CC];
__device__ __half g_xh[NROWS*CC];
__device__ __half g_yh[NROWS*CC];
__device__ float  g_q[NROWS*CC];
__device__ float  g_k[NROWS*CC];
__device__ float  g_v[NROWS*CC];
__device__ __half g_qh[NROWS*CC];
__device__ __half g_kh[NROWS*CC];
__device__ __half g_vh[NROWS*CC];
__device__ __half g_vth[(size_t)BB*HH*64*TT];   // V^T: [(b*HH+h)*64+d][t]
__device__ float  g_ga[NROWS*HH];

// ---------------- helpers ----------------------------------------------------
__device__ __forceinline__ void cp_async16(uint32_t saddr, const void* g) {
    asm volatile("cp.async.cg.shared.global [%0], [%1], 16;\n" :: "r"(saddr), "l"(g));
}
__device__ __forceinline__ void cp_commit() {
    asm volatile("cp.async.commit_group;\n");
}
__device__ __forceinline__ void cp_wait0() {
    asm volatile("cp.async.wait_group 0;\n");
}
__device__ __forceinline__ void cp_wait1() {
    asm volatile("cp.async.wait_group 1;\n");
}
__device__ __forceinline__ void mma_fp16(float c[4], uint32_t a0, uint32_t a1,
                                         uint32_t a2, uint32_t a3,
                                         uint32_t b0, uint32_t b1) {
    asm volatile(
        "mma.sync.aligned.m16n8k16.row.col.f32.f16.f16.f32 "
        "{%0,%1,%2,%3}, {%4,%5,%6,%7}, {%8,%9}, {%0,%1,%2,%3};"
        : "+f"(c[0]), "+f"(c[1]), "+f"(c[2]), "+f"(c[3])
        : "r"(a0), "r"(a1), "r"(a2), "r"(a3), "r"(b0), "r"(b1));
}

// ---------------- 0) convert x to fp16 ---------------------------------------
__global__ void round_x_kernel(const float* __restrict__ x) {
    int i = blockIdx.x * blockDim.x + threadIdx.x;
    float4 v = ((const float4*)x)[i];
    __half2 h0 = __floats2half2_rn(v.x, v.y);
    __half2 h1 = __floats2half2_rn(v.z, v.w);
    uint2 r = {*(uint32_t*)&h0, *(uint32_t*)&h1};
    ((uint2*)g_xh)[i] = r;
}

// ---------------- 1) fuse mix into weights -> fp16; wi=3 converts cpw -------
__global__ void fuse_kernel(const float* __restrict__ cq, const float* __restrict__ ck,
                            const float* __restrict__ cv, const float* __restrict__ cp,
                            const float* __restrict__ qm,
                            const float* __restrict__ km, const float* __restrict__ vm) {
    int row = blockIdx.x;
    int wi  = blockIdx.y;
    int c = threadIdx.x * 4;
    if (wi == 3) {
        float4 v = *(const float4*)&cp[row*CC + c];
        __half2 h0 = __floats2half2_rn(v.x, v.y);
        __half2 h1 = __floats2half2_rn(v.z, v.w);
        uint2 r = {*(uint32_t*)&h0, *(uint32_t*)&h1};
        *(uint2*)&g_pwh[row*CC + c] = r;
        return;
    }
    const float* W = (wi == 0) ? cq : (wi == 1) ? ck : cv;
    const float* M = (wi == 0) ? qm : (wi == 1) ? km : vm;
    __half* O      = (wi == 0) ? g_qwh : (wi == 1) ? g_kwh : g_vwh;
    int h = row >> 6, d = row & 63;
    float mx[16];
#pragma unroll
    for (int m = 0; m < 16; m++) mx[m] = M[h*16 + m];
    float4 s = {0.f, 0.f, 0.f, 0.f};
#pragma unroll
    for (int m = 0; m < 16; m++) {
        float4 w = *(const float4*)&W[(size_t)(m*64 + d)*CC + c];
        s.x += mx[m]*w.x; s.y += mx[m]*w.y;
        s.z += mx[m]*w.z; s.w += mx[m]*w.w;
    }
    __half2 h0 = __floats2half2_rn(s.x, s.y);
    __half2 h1 = __floats2half2_rn(s.z, s.w);
    uint2 r = {*(uint32_t*)&h0, *(uint32_t*)&h1};
    *(uint2*)&O[row*CC + c] = r;
}

// ---------------- 2) NT GEMM, fp16 m16n8k16, BK=32, 3-stage (proven R11) ----
#define HST 40
#define HSTG (128*HST)
#define GEMM_SMEM (3*2*HSTG*2)

__global__ __launch_bounds__(256, 2) void gemm_fp16_kernel(
    const __half* __restrict__ A,
    const __half* __restrict__ B0, float* __restrict__ C0,
    const __half* __restrict__ B1, float* __restrict__ C1,
    const __half* __restrict__ B2, float* __restrict__ C2,
    int K) {
    const __half* Bm = (blockIdx.z == 0) ? B0 : (blockIdx.z == 1) ? B1 : B2;
    float*        Cm = (blockIdx.z == 0) ? C0 : (blockIdx.z == 1) ? C1 : C2;
    const int N = CC;

    extern __shared__ __half hsm[];
    __half* Asm = hsm;
    __half* Bsm = hsm + 3*HSTG;

    const int tid  = threadIdx.x;
    const int lane = tid & 31;
    const int warp = tid >> 5;
    const int wr = warp & 1;
    const int wc = warp >> 1;
    const int g  = lane >> 2;
    const int l4 = lane & 3;
    const int brow = blockIdx.x * 128, bcol = blockIdx.y * 128;

    const int lrow = tid >> 1;
    const int lch  = (tid & 1) * 16;
    const __half* Ab = A  + (size_t)(brow + lrow) * K + lch;
    const __half* Bb = Bm + (size_t)(bcol + lrow) * K + lch;
    const uint32_t Ad = (uint32_t)__cvta_generic_to_shared(Asm + lrow*HST + lch);
    const uint32_t Bd = (uint32_t)__cvta_generic_to_shared(Bsm + lrow*HST + lch);
    const uint32_t stageB = HSTG * 2;

    const int NIT = K / 32;

#pragma unroll
    for (int s = 0; s < 2; s++) {
        cp_async16(Ad + s*stageB,      Ab + s*32);
        cp_async16(Ad + s*stageB + 16, Ab + s*32 + 8);
        cp_async16(Bd + s*stageB,      Bb + s*32);
        cp_async16(Bd + s*stageB + 16, Bb + s*32 + 8);
        cp_commit();
    }

    float acc[4][4][4];
#pragma unroll
    for (int mi = 0; mi < 4; mi++)
#pragma unroll
        for (int ni = 0; ni < 4; ni++)
#pragma unroll
            for (int r = 0; r < 4; r++) acc[mi][ni][r] = 0.f;

    for (int it = 0; it < NIT; it++) {
        if (it + 1 < NIT) cp_wait1(); else cp_wait0();
        __syncthreads();
        if (it + 2 < NIT) {
            int s = (it + 2) % 3;
            cp_async16(Ad + s*stageB,      Ab + (it+2)*32);
            cp_async16(Ad + s*stageB + 16, Ab + (it+2)*32 + 8);
            cp_async16(Bd + s*stageB,      Bb + (it+2)*32);
            cp_async16(Bd + s*stageB + 16, Bb + (it+2)*32 + 8);
            cp_commit();
        }
        const uint32_t* Aw = (const uint32_t*)(Asm + (it % 3)*HSTG);
        const uint32_t* Bw = (const uint32_t*)(Bsm + (it % 3)*HSTG);
#pragma unroll
        for (int ks = 0; ks < 2; ks++) {
            const int k0w = ks*8;
            uint32_t bf[4][2];
#pragma unroll
            for (int ni = 0; ni < 4; ni++) {
                const uint32_t* bp = Bw + (wc*32 + ni*8 + g)*20 + k0w + l4;
                bf[ni][0] = bp[0];
                bf[ni][1] = bp[4];
            }
#pragma unroll
            for (int mi = 0; mi < 4; mi++) {
                const uint32_t* ap0 = Aw + (wr*64 + mi*16 + g)*20 + k0w + l4;
                const uint32_t* ap1 = ap0 + 8*20;
                uint32_t a0 = ap0[0];
                uint32_t a1 = ap1[0];
                uint32_t a2 = ap0[4];
                uint32_t a3 = ap1[4];
#pragma unroll
                for (int ni = 0; ni < 4; ni++)
                    mma_fp16(acc[mi][ni], a0, a1, a2, a3, bf[ni][0], bf[ni][1]);
            }
        }
    }

#pragma unroll
    for (int mi = 0; mi < 4; mi++) {
#pragma unroll
        for (int ni = 0; ni < 4; ni++) {
            int row0 = brow + wr*64 + mi*16 + g;
            int col  = bcol + wc*32 + ni*8 + 2*l4;
            float2 w0 = {acc[mi][ni][0], acc[mi][ni][1]};
            float2 w1 = {acc[mi][ni][2], acc[mi][ni][3]};
            *(float2*)(Cm + (size_t)row0 * N + col)       = w0;
            *(float2*)(Cm + (size_t)(row0 + 8) * N + col) = w1;
        }
    }
}

// ---------------- 3) gates + RoPE + RMSNorm -> fp16 q/k/v -------------------
__global__ void post_kernel(const float* __restrict__ x, const float* __restrict__ ve,
                            const float* __restrict__ cosb, const float* __restrict__ sinb,
                            const float* __restrict__ vgw, const float* __restrict__ agw) {
    int gw   = (blockIdx.x * blockDim.x + threadIdx.x) >> 5;
    int lane = threadIdx.x & 31;
    if (gw >= NROWS*HH) return;
    int h  = gw % HH;
    int bt = gw / HH;
    int t  = bt % TT;
    size_t xbase = (size_t)bt * CC;

    float gv = x[xbase + lane] * vgw[h*32 + lane];
#pragma unroll
    for (int o = 16; o > 0; o >>= 1) gv += __shfl_xor_sync(0xffffffffu, gv, o);
    float gate_v = 2.f / (1.f + __expf(-gv));

    float ga = (lane < 12) ? x[xbase + lane] * agw[h*12 + lane] : 0.f;
#pragma unroll
    for (int o = 16; o > 0; o >>= 1) ga += __shfl_xor_sync(0xffffffffu, ga, o);
    if (lane == 0) g_ga[(size_t)bt*HH + h] = 1.f / (1.f + __expf(-ga));

    size_t idx = xbase + h*64;
    float v1 = g_v[idx + lane]      + gate_v * ve[idx + lane];
    float v2 = g_v[idx + lane + 32] + gate_v * ve[idx + lane + 32];
    g_vh[idx + lane]      = __float2half_rn(v1);
    g_vh[idx + lane + 32] = __float2half_rn(v2);

    float cs = cosb[t*32 + lane], sn = sinb[t*32 + lane];
    {
        float q1 = g_q[idx + lane], q2 = g_q[idx + lane + 32];
        float r1 =  q1*cs + q2*sn;
        float r2 = -q1*sn + q2*cs;
        float ss = r1*r1 + r2*r2;
#pragma unroll
        for (int o = 16; o > 0; o >>= 1) ss += __shfl_xor_sync(0xffffffffu, ss, o);
        float sc = rsqrtf(ss * (1.f/64.f) + 1e-6f);
        g_qh[idx + lane]      = __float2half_rn(r1*sc);
        g_qh[idx + lane + 32] = __float2half_rn(r2*sc);
    }
    {
        float k1 = g_k[idx + lane], k2 = g_k[idx + lane + 32];
        float r1 =  k1*cs + k2*sn;
        float r2 = -k1*sn + k2*cs;
        float ss = r1*r1 + r2*r2;
#pragma unroll
        for (int o = 16; o > 0; o >>= 1) ss += __shfl_xor_sync(0xffffffffu, ss, o);
        float sc = rsqrtf(ss * (1.f/64.f) + 1e-6f);
        g_kh[idx + lane]      = __float2half_rn(r1*sc);
        g_kh[idx + lane + 32] = __float2half_rn(r2*sc);
    }
}

// ---------------- 3b) transpose V -> V^T (fp16) ------------------------------
__global__ void vtrans_kernel() {
    __shared__ __half ts[64][65];
    const int tbk = blockIdx.x, h = blockIdx.y, b = blockIdx.z;
    const int tid = threadIdx.x;
    const size_t bT = (size_t)b*TT;
    const int t0 = tbk*64;
#pragma unroll
    for (int i = 0; i < 8; i++) {
        int w = tid + i*256;
        int t = w >> 5, dp = w & 31;
        uint32_t v = *(const uint32_t*)(g_vh + (bT + t0 + t)*CC + h*64 + 2*dp);
        __half2 hv = *(__half2*)&v;
        ts[2*dp][t]   = __low2half(hv);
        ts[2*dp+1][t] = __high2half(hv);
    }
    __syncthreads();
    const size_t vbase = ((size_t)(b*HH + h))*64;
#pragma unroll
    for (int i = 0; i < 8; i++) {
        int w = tid + i*256;
        int d = w >> 5, tp = w & 31;
        __half2 hv = __halves2half2(ts[d][2*tp], ts[d][2*tp+1]);
        *(uint32_t*)(g_vth + (vbase + d)*TT + t0 + 2*tp) = *(uint32_t*)&hv;
    }
}

// ---------------- 4) flash attention via fp16 mma, BM=128, BN=64 ------------
#define ASTH 72
#define ATTN_SMEM ((128*ASTH + 4*64*ASTH)*2)   // 55296 B

__global__ __launch_bounds__(256, 2) void attn_kernel(const int* __restrict__ wsp) {
    extern __shared__ __half ash[];
    __half* Qs = ash;                        // [128][ASTH], P overlays
    __half* Ks = ash + 128*ASTH;             // [2][64][ASTH]
    __half* Vs = Ks  + 2*64*ASTH;            // [2][64][ASTH]  (V^T: row=d, col=kv)

    const int qtb = (TT/128 - 1) - blockIdx.x;
    const int h = blockIdx.y, b = blockIdx.z;
    const int tid  = threadIdx.x;
    const int lane = tid & 31;
    const int w    = tid >> 5;
    const int g    = lane >> 2;
    const int l4   = lane & 3;
    const int q0   = qtb * 128;
    const int hoff = h*64;
    const size_t bT = (size_t)b*TT;
    const size_t vbase = ((size_t)(b*HH + h))*64;

    int wsv = wsp ? *wsp : -1;
    const bool use_w = (wsv >= 0) && (wsv < TT - 1);
    int jt0 = 0;
    if (use_w) {
        int lo = q0 - wsv - 63;
        if (lo > 0) jt0 = (lo + 63) >> 6;
    }
    const int jtmax = 2*qtb + 1;

    // prologue: Q (group 1)
    {
        int row = tid >> 1;
        int c0  = (tid & 1) * 4;
        const __half* src = g_qh + (bT + q0 + row)*CC + hoff;
        uint32_t dst = (uint32_t)__cvta_generic_to_shared(Qs + row*ASTH);
#pragma unroll
        for (int i = 0; i < 4; i++) cp_async16(dst + (c0 + i)*16, src + (c0 + i)*8);
        cp_commit();
    }
    // prologue: K (shifted halves) + V^T for jt0 (group 2)
    {
        int r  = tid >> 2;
        int c0 = (tid & 3) * 2;
        int pos = jt0*64 + r;
        int sh  = (pos > 0) ? pos - 1 : 0;
        uint32_t kd = (uint32_t)__cvta_generic_to_shared(Ks + (jt0&1)*64*ASTH + r*ASTH);
        uint32_t vd = (uint32_t)__cvta_generic_to_shared(Vs + (jt0&1)*64*ASTH + r*ASTH);
        const __half* kp  = g_kh + (bT + pos)*CC + hoff;
        const __half* ksh = g_kh + (bT + sh)*CC + hoff;
        const __half* vp  = g_vth + (vbase + r)*TT + jt0*64;
#pragma unroll
        for (int i = 0; i < 2; i++) {
            int c = c0 + i;
            const __half* kb = (c < 4) ? kp : ksh;   // halves 0-31 = chunks 0-3 (d<32)
            cp_async16(kd + c*16, kb + c*8);
            cp_async16(vd + c*16, vp + c*8);
        }
        cp_commit();
    }

    // Q fragments into registers
    uint32_t qa[4][4];
    cp_wait1();
    __syncthreads();
    {
        const __half* q0p = Qs + (16*w + g)*ASTH;
        const __half* q1p = q0p + 8*ASTH;
#pragma unroll
        for (int ks = 0; ks < 4; ks++) {
            qa[ks][0] = *(const uint32_t*)(q0p + 16*ks + 2*l4);
            qa[ks][1] = *(const uint32_t*)(q1p + 16*ks + 2*l4);
            qa[ks][2] = *(const uint32_t*)(q0p + 16*ks + 2*l4 + 8);
            qa[ks][3] = *(const uint32_t*)(q1p + 16*ks + 2*l4 + 8);
        }
    }
    __syncwarp();

    float oacc[8][4];
#pragma unroll
    for (int nt = 0; nt < 8; nt++)
#pragma unroll
        for (int r = 0; r < 4; r++) oacc[nt][r] = 0.f;
    float mi0 = -1e30f, mi1 = -1e30f, li0 = 0.f, li1 = 0.f;

    const int wrmin = q0 + 16*w;
    const int wrmax = wrmin + 15;
    const int r0g   = wrmin + g;
    const int r1g   = r0g + 8;
    uint32_t* Pw0 = (uint32_t*)(Qs + (16*w + g)*ASTH);
    uint32_t* Pw1 = (uint32_t*)(Qs + (16*w + g + 8)*ASTH);

    for (int jt = jt0; jt <= jtmax; jt++) {
        const int kv0 = jt * 64;
        const int buf = jt & 1;
        cp_wait0();
        __syncthreads();

        // prefetch K/V[jt+1]
        if (jt < jtmax) {
            int r  = tid >> 2;
            int c0 = (tid & 3) * 2;
            int pos = kv0 + 64 + r;
            uint32_t kd = (uint32_t)__cvta_generic_to_shared(Ks + (buf^1)*64*ASTH + r*ASTH);
            uint32_t vd = (uint32_t)__cvta_generic_to_shared(Vs + (buf^1)*64*ASTH + r*ASTH);
            const __half* kp  = g_kh + (bT + pos)*CC + hoff;
            const __half* ksh = g_kh + (bT + pos - 1)*CC + hoff;
            const __half* vp  = g_vth + (vbase + r)*TT + kv0 + 64;
#pragma unroll
            for (int i = 0; i < 2; i++) {
                int c = c0 + i;
                const __half* kb = (c < 4) ? kp : ksh;
                cp_async16(kd + c*16, kb + c*8);
                cp_async16(vd + c*16, vp + c*8);
            }
            cp_commit();
        }

        bool dead = (kv0 > wrmax) || (use_w && (kv0 + 63 < wrmin - wsv));
        if (!dead) {
            const __half* Kb = Ks + buf*64*ASTH;
            const __half* Vb = Vs + buf*64*ASTH;

            // S = Q K^T (fp16 m16n8k16)
            float sacc[8][4];
#pragma unroll
            for (int nt = 0; nt < 8; nt++)
#pragma unroll
                for (int r = 0; r < 4; r++) sacc[nt][r] = 0.f;
#pragma unroll
            for (int ks = 0; ks < 4; ks++) {
#pragma unroll
                for (int nt = 0; nt < 8; nt++) {
                    const __half* kp2 = Kb + (8*nt + g)*ASTH + 16*ks + 2*l4;
                    uint32_t b0 = *(const uint32_t*)kp2;
                    uint32_t b1 = *(const uint32_t*)(kp2 + 8);
                    mma_fp16(sacc[nt], qa[ks][0], qa[ks][1], qa[ks][2], qa[ks][3], b0, b1);
                }
            }

            const bool full = (kv0 + 63 <= wrmin) &&
                              (!use_w || (wrmax - kv0 <= wsv));
            if (full) {
#pragma unroll
                for (int nt = 0; nt < 8; nt++)
#pragma unroll
                    for (int r = 0; r < 4; r++) sacc[nt][r] *= 0.125f;
            } else {
#pragma unroll
                for (int nt = 0; nt < 8; nt++) {
                    int c0 = kv0 + 8*nt + 2*l4;
#pragma unroll
                    for (int r = 0; r < 4; r++) {
                        int qi = (r < 2) ? r0g : r1g;
                        int kj = c0 + (r & 1);
                        bool ok = (kj <= qi) && (!use_w || (qi - kj) <= wsv);
                        sacc[nt][r] = ok ? sacc[nt][r]*0.125f : -1e30f;
                    }
                }
            }

            float mx0 = -1e30f, mx1 = -1e30f;
#pragma unroll
            for (int nt = 0; nt < 8; nt++) {
                mx0 = fmaxf(mx0, fmaxf(sacc[nt][0], sacc[nt][1]));
                mx1 = fmaxf(mx1, fmaxf(sacc[nt][2], sacc[nt][3]));
            }
            mx0 = fmaxf(mx0, __shfl_xor_sync(0xffffffffu, mx0, 1));
            mx0 = fmaxf(mx0, __shfl_xor_sync(0xffffffffu, mx0, 2));
            mx1 = fmaxf(mx1, __shfl_xor_sync(0xffffffffu, mx1, 1));
            mx1 = fmaxf(mx1, __shfl_xor_sync(0xffffffffu, mx1, 2));
            float mn0 = fmaxf(fmaxf(mi0, mx0), -1e29f);
            float mn1 = fmaxf(fmaxf(mi1, mx1), -1e29f);
            float corr0 = __expf(mi0 - mn0);
            float corr1 = __expf(mi1 - mn1);
            float sum0 = 0.f, sum1 = 0.f;
#pragma unroll
            for (int nt = 0; nt < 8; nt++) {
                float p0 = __expf(sacc[nt][0] - mn0);
                float p1 = __expf(sacc[nt][1] - mn0);
                float p2 = __expf(sacc[nt][2] - mn1);
                float p3 = __expf(sacc[nt][3] - mn1);
                sum0 += p0 + p1; sum1 += p2 + p3;
                __half2 hp0 = __floats2half2_rn(p0, p1);
                __half2 hp1 = __floats2half2_rn(p2, p3);
                Pw0[4*nt + l4] = *(uint32_t*)&hp0;
                Pw1[4*nt + l4] = *(uint32_t*)&hp1;
            }
            sum0 += __shfl_xor_sync(0xffffffffu, sum0, 1);
            sum0 += __shfl_xor_sync(0xffffffffu, sum0, 2);
            sum1 += __shfl_xor_sync(0xffffffffu, sum1, 1);
            sum1 += __shfl_xor_sync(0xffffffffu, sum1, 2);
            li0 = li0*corr0 + sum0;
            li1 = li1*corr1 + sum1;
            mi0 = mn0; mi1 = mn1;
#pragma unroll
            for (int nt = 0; nt < 8; nt++) {
                oacc[nt][0] *= corr0; oacc[nt][1] *= corr0;
                oacc[nt][2] *= corr1; oacc[nt][3] *= corr1;
            }
            __syncwarp();

            // O += P V  (fp16 m16n8k16; B from V^T rows)
#pragma unroll
            for (int ks = 0; ks < 4; ks++) {
                uint32_t a0 = Pw0[8*ks + l4];
                uint32_t a1 = Pw1[8*ks + l4];
                uint32_t a2 = Pw0[8*ks + l4 + 4];
                uint32_t a3 = Pw1[8*ks + l4 + 4];
#pragma unroll
                for (int nt = 0; nt < 8; nt++) {
                    const __half* vp2 = Vb + (8*nt + g)*ASTH + 16*ks + 2*l4;
                    uint32_t b0 = *(const uint32_t*)vp2;
                    uint32_t b1 = *(const uint32_t*)(vp2 + 8);
                    mma_fp16(oacc[nt], a0, a1, a2, a3, b0, b1);
                }
            }
            __syncwarp();
        }
    }

    // epilogue: normalize, gate, write y as fp16
    float ga0 = g_ga[(bT + r0g)*HH + h];
    float ga1 = g_ga[(bT + r1g)*HH + h];
    float inv0 = ga0 / li0;
    float inv1 = ga1 / li1;
    __half* y0 = g_yh + (bT + r0g)*CC + hoff;
    __half* y1 = g_yh + (bT + r1g)*CC + hoff;
#pragma unroll
    for (int nt = 0; nt < 8; nt++) {
        int c = 8*nt + 2*l4;
        __half2 w0 = __floats2half2_rn(oacc[nt][0]*inv0, oacc[nt][1]*inv0);
        __half2 w1 = __floats2half2_rn(oacc[nt][2]*inv1, oacc[nt][3]*inv1);
        *(__half2*)(y0 + c) = w0;
        *(__half2*)(y1 + c) = w1;
    }
}

// ---------------- launch ----------------------------------------------------
extern "C" void kernel_launch(void* const* d_in, const int* in_sizes, int n_in,
                              void* d_out, int out_size) {
    const float* x    = (const float*)d_in[0];
    const float* ve   = (const float*)d_in[1];
    const float* cosb = (const float*)d_in[2];
    const float* sinb = (const float*)d_in[3];
    const float* cqw  = (const float*)d_in[4];
    const float* ckw  = (const float*)d_in[5];
    const float* cvw  = (const float*)d_in[6];
    const float* cpw  = (const float*)d_in[7];
    const float* vgw  = (const float*)d_in[8];
    const float* agw  = (const float*)d_in[9];
    const float* qm   = (const float*)d_in[10];
    const float* km   = (const float*)d_in[11];
    const float* vm   = (const float*)d_in[12];
    const int*   wsp  = (n_in > 13) ? (const int*)d_in[13] : nullptr;
    float* out = (float*)d_out;

    __half *pqwh, *pkwh, *pvwh, *ppwh, *pxh, *pyh;
    float *pq, *pk, *pv;
    cudaGetSymbolAddress((void**)&pqwh, g_qwh);
    cudaGetSymbolAddress((void**)&pkwh, g_kwh);
    cudaGetSymbolAddress((void**)&pvwh, g_vwh);
    cudaGetSymbolAddress((void**)&ppwh, g_pwh);
    cudaGetSymbolAddress((void**)&pxh,  g_xh);
    cudaGetSymbolAddress((void**)&pyh,  g_yh);
    cudaGetSymbolAddress((void**)&pq,   g_q);
    cudaGetSymbolAddress((void**)&pk,   g_k);
    cudaGetSymbolAddress((void**)&pv,   g_v);

    // 0) convert x to fp16
    round_x_kernel<<<NROWS*CC/1024, 256>>>(x);

    // 1) fuse mixes into weights (fp16) + convert cpw
    fuse_kernel<<<dim3(CC, 4), 256>>>(cqw, ckw, cvw, cpw, qm, km, vm);

    // 2) QKV projections (fp16 mma)
    cudaFuncSetAttribute(gemm_fp16_kernel, cudaFuncAttributeMaxDynamicSharedMemorySize, GEMM_SMEM);
    gemm_fp16_kernel<<<dim3(NROWS/128, CC/128, 3), 256, GEMM_SMEM>>>(
        pxh, pqwh, pq, pkwh, pk, pvwh, pv, CC);

    // 3) gates + rope + rmsnorm -> fp16 q/k/v
    post_kernel<<<(NROWS*HH*32)/256, 256>>>(x, ve, cosb, sinb, vgw, agw);

    // 3b) V transpose
    vtrans_kernel<<<dim3(TT/64, HH, BB), 256>>>();

    // 4) flash attention (fp16 mma)
    cudaFuncSetAttribute(attn_kernel, cudaFuncAttributeMaxDynamicSharedMemorySize, ATTN_SMEM);
    attn_kernel<<<dim3(TT/128, HH, BB), 256, ATTN_SMEM>>>(wsp);

    // 5) output projection (fp16 mma)
    gemm_fp16_kernel<<<dim3(NROWS/128, CC/128, 1), 256, GEMM_SMEM>>>(
        pyh, ppwh, out, ppwh, out, ppwh, out, CC);
}

// round 14
// speedup vs baseline: 2.0047x; 1.0061x over previous
#include <cuda_runtime.h>
#include <cuda_fp16.h>
#include <cstdint>
#include <cstddef>
#include <math.h>

#define BB 2
#define TT 2048
#define CC 1024
#define HH 16
#define NROWS (BB*TT)   // 4096

// ---------------- scratch (static device allocations; no cudaMalloc) -------
__device__ __half g_qwh[CC*CC];
__device__ __half g_kwh[CC*CC];
__device__ __half g_vwh[CC*CC];
__device__ __half g_pwh[CC*CC];
__device__ __half g_xh[NROWS*CC];
__device__ __half g_yh[NROWS*CC];
__device__ __half g_qh[NROWS*CC];
__device__ __half g_kh[NROWS*CC];
__device__ __half g_vh[NROWS*CC];
__device__ __half g_vth[(size_t)BB*HH*64*TT];   // V^T: [(b*HH+h)*64+d][t]
__device__ float  g_ga[NROWS*HH];

// ---------------- helpers ----------------------------------------------------
__device__ __forceinline__ void cp_async16(uint32_t saddr, const void* g) {
    asm volatile("cp.async.cg.shared.global [%0], [%1], 16;\n" :: "r"(saddr), "l"(g));
}
__device__ __forceinline__ void cp_commit() {
    asm volatile("cp.async.commit_group;\n");
}
__device__ __forceinline__ void cp_wait0() {
    asm volatile("cp.async.wait_group 0;\n");
}
__device__ __forceinline__ void cp_wait1() {
    asm volatile("cp.async.wait_group 1;\n");
}
__device__ __forceinline__ void mma_fp16(float c[4], uint32_t a0, uint32_t a1,
                                         uint32_t a2, uint32_t a3,
                                         uint32_t b0, uint32_t b1) {
    asm volatile(
        "mma.sync.aligned.m16n8k16.row.col.f32.f16.f16.f32 "
        "{%0,%1,%2,%3}, {%4,%5,%6,%7}, {%8,%9}, {%0,%1,%2,%3};"
        : "+f"(c[0]), "+f"(c[1]), "+f"(c[2]), "+f"(c[3])
        : "r"(a0), "r"(a1), "r"(a2), "r"(a3), "r"(b0), "r"(b1));
}

// ---------------- 0) convert x to fp16 ---------------------------------------
__global__ void round_x_kernel(const float* __restrict__ x) {
    int i = blockIdx.x * blockDim.x + threadIdx.x;
    float4 v = ((const float4*)x)[i];
    __half2 h0 = __floats2half2_rn(v.x, v.y);
    __half2 h1 = __floats2half2_rn(v.z, v.w);
    uint2 r = {*(uint32_t*)&h0, *(uint32_t*)&h1};
    ((uint2*)g_xh)[i] = r;
}

// ---------------- 1) fuse mix into weights -> fp16; wi=3 converts cpw -------
__global__ void fuse_kernel(const float* __restrict__ cq, const float* __restrict__ ck,
                            const float* __restrict__ cv, const float* __restrict__ cp,
                            const float* __restrict__ qm,
                            const float* __restrict__ km, const float* __restrict__ vm) {
    int row = blockIdx.x;
    int wi  = blockIdx.y;
    int c = threadIdx.x * 4;
    if (wi == 3) {
        float4 v = *(const float4*)&cp[row*CC + c];
        __half2 h0 = __floats2half2_rn(v.x, v.y);
        __half2 h1 = __floats2half2_rn(v.z, v.w);
        uint2 r = {*(uint32_t*)&h0, *(uint32_t*)&h1};
        *(uint2*)&g_pwh[row*CC + c] = r;
        return;
    }
    const float* W = (wi == 0) ? cq : (wi == 1) ? ck : cv;
    const float* M = (wi == 0) ? qm : (wi == 1) ? km : vm;
    __half* O      = (wi == 0) ? g_qwh : (wi == 1) ? g_kwh : g_vwh;
    int h = row >> 6, d = row & 63;
    float mx[16];
#pragma unroll
    for (int m = 0; m < 16; m++) mx[m] = M[h*16 + m];
    float4 s = {0.f, 0.f, 0.f, 0.f};
#pragma unroll
    for (int m = 0; m < 16; m++) {
        float4 w = *(const float4*)&W[(size_t)(m*64 + d)*CC + c];
        s.x += mx[m]*w.x; s.y += mx[m]*w.y;
        s.z += mx[m]*w.z; s.w += mx[m]*w.w;
    }
    __half2 h0 = __floats2half2_rn(s.x, s.y);
    __half2 h1 = __floats2half2_rn(s.z, s.w);
    uint2 r = {*(uint32_t*)&h0, *(uint32_t*)&h1};
    *(uint2*)&O[row*CC + c] = r;
}

// ---------------- 2) NT GEMM, fp16 m16n8k16, BK=32, 3-stage; output T -------
#define HST 40
#define HSTG (128*HST)
#define GEMM_SMEM (3*2*HSTG*2)

template <typename TO>
__global__ __launch_bounds__(256, 2) void gemm_fp16_kernel(
    const __half* __restrict__ A,
    const __half* __restrict__ B0, TO* __restrict__ C0,
    const __half* __restrict__ B1, TO* __restrict__ C1,
    const __half* __restrict__ B2, TO* __restrict__ C2,
    int K) {
    const __half* Bm = (blockIdx.z == 0) ? B0 : (blockIdx.z == 1) ? B1 : B2;
    TO*           Cm = (blockIdx.z == 0) ? C0 : (blockIdx.z == 1) ? C1 : C2;
    const int N = CC;

    extern __shared__ __half hsm[];
    __half* Asm = hsm;
    __half* Bsm = hsm + 3*HSTG;

    const int tid  = threadIdx.x;
    const int lane = tid & 31;
    const int warp = tid >> 5;
    const int wr = warp & 1;
    const int wc = warp >> 1;
    const int g  = lane >> 2;
    const int l4 = lane & 3;
    const int brow = blockIdx.x * 128, bcol = blockIdx.y * 128;

    const int lrow = tid >> 1;
    const int lch  = (tid & 1) * 16;
    const __half* Ab = A  + (size_t)(brow + lrow) * K + lch;
    const __half* Bb = Bm + (size_t)(bcol + lrow) * K + lch;
    const uint32_t Ad = (uint32_t)__cvta_generic_to_shared(Asm + lrow*HST + lch);
    const uint32_t Bd = (uint32_t)__cvta_generic_to_shared(Bsm + lrow*HST + lch);
    const uint32_t stageB = HSTG * 2;

    const int NIT = K / 32;

#pragma unroll
    for (int s = 0; s < 2; s++) {
        cp_async16(Ad + s*stageB,      Ab + s*32);
        cp_async16(Ad + s*stageB + 16, Ab + s*32 + 8);
        cp_async16(Bd + s*stageB,      Bb + s*32);
        cp_async16(Bd + s*stageB + 16, Bb + s*32 + 8);
        cp_commit();
    }

    float acc[4][4][4];
#pragma unroll
    for (int mi = 0; mi < 4; mi++)
#pragma unroll
        for (int ni = 0; ni < 4; ni++)
#pragma unroll
            for (int r = 0; r < 4; r++) acc[mi][ni][r] = 0.f;

    for (int it = 0; it < NIT; it++) {
        if (it + 1 < NIT) cp_wait1(); else cp_wait0();
        __syncthreads();
        if (it + 2 < NIT) {
            int s = (it + 2) % 3;
            cp_async16(Ad + s*stageB,      Ab + (it+2)*32);
            cp_async16(Ad + s*stageB + 16, Ab + (it+2)*32 + 8);
            cp_async16(Bd + s*stageB,      Bb + (it+2)*32);
            cp_async16(Bd + s*stageB + 16, Bb + (it+2)*32 + 8);
            cp_commit();
        }
        const uint32_t* Aw = (const uint32_t*)(Asm + (it % 3)*HSTG);
        const uint32_t* Bw = (const uint32_t*)(Bsm + (it % 3)*HSTG);
#pragma unroll
        for (int ks = 0; ks < 2; ks++) {
            const int k0w = ks*8;
            uint32_t bf[4][2];
#pragma unroll
            for (int ni = 0; ni < 4; ni++) {
                const uint32_t* bp = Bw + (wc*32 + ni*8 + g)*20 + k0w + l4;
                bf[ni][0] = bp[0];
                bf[ni][1] = bp[4];
            }
#pragma unroll
            for (int mi = 0; mi < 4; mi++) {
                const uint32_t* ap0 = Aw + (wr*64 + mi*16 + g)*20 + k0w + l4;
                const uint32_t* ap1 = ap0 + 8*20;
                uint32_t a0 = ap0[0];
                uint32_t a1 = ap1[0];
                uint32_t a2 = ap0[4];
                uint32_t a3 = ap1[4];
#pragma unroll
                for (int ni = 0; ni < 4; ni++)
                    mma_fp16(acc[mi][ni], a0, a1, a2, a3, bf[ni][0], bf[ni][1]);
            }
        }
    }

#pragma unroll
    for (int mi = 0; mi < 4; mi++) {
#pragma unroll
        for (int ni = 0; ni < 4; ni++) {
            int row0 = brow + wr*64 + mi*16 + g;
            int col  = bcol + wc*32 + ni*8 + 2*l4;
            if (sizeof(TO) == 4) {
                float2 w0 = {acc[mi][ni][0], acc[mi][ni][1]};
                float2 w1 = {acc[mi][ni][2], acc[mi][ni][3]};
                *(float2*)((float*)Cm + (size_t)row0 * N + col)       = w0;
                *(float2*)((float*)Cm + (size_t)(row0 + 8) * N + col) = w1;
            } else {
                __half2 w0 = __floats2half2_rn(acc[mi][ni][0], acc[mi][ni][1]);
                __half2 w1 = __floats2half2_rn(acc[mi][ni][2], acc[mi][ni][3]);
                *(__half2*)((__half*)Cm + (size_t)row0 * N + col)       = w0;
                *(__half2*)((__half*)Cm + (size_t)(row0 + 8) * N + col) = w1;
            }
        }
    }
}

// ---------------- 3) gates + RoPE + RMSNorm; fp16 in/out --------------------
__global__ void post_kernel(const float* __restrict__ x, const float* __restrict__ ve,
                            const float* __restrict__ cosb, const float* __restrict__ sinb,
                            const float* __restrict__ vgw, const float* __restrict__ agw) {
    int gw   = (blockIdx.x * blockDim.x + threadIdx.x) >> 5;
    int lane = threadIdx.x & 31;
    if (gw >= NROWS*HH) return;
    int h  = gw % HH;
    int bt = gw / HH;
    int t  = bt % TT;
    size_t xbase = (size_t)bt * CC;

    float gv = x[xbase + lane] * vgw[h*32 + lane];
#pragma unroll
    for (int o = 16; o > 0; o >>= 1) gv += __shfl_xor_sync(0xffffffffu, gv, o);
    float gate_v = 2.f / (1.f + __expf(-gv));

    float ga = (lane < 12) ? x[xbase + lane] * agw[h*12 + lane] : 0.f;
#pragma unroll
    for (int o = 16; o > 0; o >>= 1) ga += __shfl_xor_sync(0xffffffffu, ga, o);
    if (lane == 0) g_ga[(size_t)bt*HH + h] = 1.f / (1.f + __expf(-ga));

    size_t idx = xbase + h*64;
    float v1 = __half2float(g_vh[idx + lane])      + gate_v * ve[idx + lane];
    float v2 = __half2float(g_vh[idx + lane + 32]) + gate_v * ve[idx + lane + 32];
    g_vh[idx + lane]      = __float2half_rn(v1);
    g_vh[idx + lane + 32] = __float2half_rn(v2);

    float cs = cosb[t*32 + lane], sn = sinb[t*32 + lane];
    {
        float q1 = __half2float(g_qh[idx + lane]);
        float q2 = __half2float(g_qh[idx + lane + 32]);
        float r1 =  q1*cs + q2*sn;
        float r2 = -q1*sn + q2*cs;
        float ss = r1*r1 + r2*r2;
#pragma unroll
        for (int o = 16; o > 0; o >>= 1) ss += __shfl_xor_sync(0xffffffffu, ss, o);
        float sc = rsqrtf(ss * (1.f/64.f) + 1e-6f);
        g_qh[idx + lane]      = __float2half_rn(r1*sc);
        g_qh[idx + lane + 32] = __float2half_rn(r2*sc);
    }
    {
        float k1 = __half2float(g_kh[idx + lane]);
        float k2 = __half2float(g_kh[idx + lane + 32]);
        float r1 =  k1*cs + k2*sn;
        float r2 = -k1*sn + k2*cs;
        float ss = r1*r1 + r2*r2;
#pragma unroll
        for (int o = 16; o > 0; o >>= 1) ss += __shfl_xor_sync(0xffffffffu, ss, o);
        float sc = rsqrtf(ss * (1.f/64.f) + 1e-6f);
        g_kh[idx + lane]      = __float2half_rn(r1*sc);
        g_kh[idx + lane + 32] = __float2half_rn(r2*sc);
    }
}

// ---------------- 3b) transpose V -> V^T (fp16) ------------------------------
__global__ void vtrans_kernel() {
    __shared__ __half ts[64][65];
    const int tbk = blockIdx.x, h = blockIdx.y, b = blockIdx.z;
    const int tid = threadIdx.x;
    const size_t bT = (size_t)b*TT;
    const int t0 = tbk*64;
#pragma unroll
    for (int i = 0; i < 8; i++) {
        int w = tid + i*256;
        int t = w >> 5, dp = w & 31;
        uint32_t v = *(const uint32_t*)(g_vh + (bT + t0 + t)*CC + h*64 + 2*dp);
        __half2 hv = *(__half2*)&v;
        ts[2*dp][t]   = __low2half(hv);
        ts[2*dp+1][t] = __high2half(hv);
    }
    __syncthreads();
    const size_t vbase = ((size_t)(b*HH + h))*64;
#pragma unroll
    for (int i = 0; i < 8; i++) {
        int w = tid + i*256;
        int d = w >> 5, tp = w & 31;
        __half2 hv = __halves2half2(ts[d][2*tp], ts[d][2*tp+1]);
        *(uint32_t*)(g_vth + (vbase + d)*TT + t0 + 2*tp) = *(uint32_t*)&hv;
    }
}

// ---------------- 4) flash attention via fp16 mma (proven R13) --------------
#define ASTH 72
#define ATTN_SMEM ((128*ASTH + 4*64*ASTH)*2)   // 55296 B

__global__ __launch_bounds__(256, 2) void attn_kernel(const int* __restrict__ wsp) {
    extern __shared__ __half ash[];
    __half* Qs = ash;
    __half* Ks = ash + 128*ASTH;
    __half* Vs = Ks  + 2*64*ASTH;

    const int qtb = (TT/128 - 1) - blockIdx.x;
    const int h = blockIdx.y, b = blockIdx.z;
    const int tid  = threadIdx.x;
    const int lane = tid & 31;
    const int w    = tid >> 5;
    const int g    = lane >> 2;
    const int l4   = lane & 3;
    const int q0   = qtb * 128;
    const int hoff = h*64;
    const size_t bT = (size_t)b*TT;
    const size_t vbase = ((size_t)(b*HH + h))*64;

    int wsv = wsp ? *wsp : -1;
    const bool use_w = (wsv >= 0) && (wsv < TT - 1);
    int jt0 = 0;
    if (use_w) {
        int lo = q0 - wsv - 63;
        if (lo > 0) jt0 = (lo + 63) >> 6;
    }
    const int jtmax = 2*qtb + 1;

    {
        int row = tid >> 1;
        int c0  = (tid & 1) * 4;
        const __half* src = g_qh + (bT + q0 + row)*CC + hoff;
        uint32_t dst = (uint32_t)__cvta_generic_to_shared(Qs + row*ASTH);
#pragma unroll
        for (int i = 0; i < 4; i++) cp_async16(dst + (c0 + i)*16, src + (c0 + i)*8);
        cp_commit();
    }
    {
        int r  = tid >> 2;
        int c0 = (tid & 3) * 2;
        int pos = jt0*64 + r;
        int sh  = (pos > 0) ? pos - 1 : 0;
        uint32_t kd = (uint32_t)__cvta_generic_to_shared(Ks + (jt0&1)*64*ASTH + r*ASTH);
        uint32_t vd = (uint32_t)__cvta_generic_to_shared(Vs + (jt0&1)*64*ASTH + r*ASTH);
        const __half* kp  = g_kh + (bT + pos)*CC + hoff;
        const __half* ksh = g_kh + (bT + sh)*CC + hoff;
        const __half* vp  = g_vth + (vbase + r)*TT + jt0*64;
#pragma unroll
        for (int i = 0; i < 2; i++) {
            int c = c0 + i;
            const __half* kb = (c < 4) ? kp : ksh;
            cp_async16(kd + c*16, kb + c*8);
            cp_async16(vd + c*16, vp + c*8);
        }
        cp_commit();
    }

    uint32_t qa[4][4];
    cp_wait1();
    __syncthreads();
    {
        const __half* q0p = Qs + (16*w + g)*ASTH;
        const __half* q1p = q0p + 8*ASTH;
#pragma unroll
        for (int ks = 0; ks < 4; ks++) {
            qa[ks][0] = *(const uint32_t*)(q0p + 16*ks + 2*l4);
            qa[ks][1] = *(const uint32_t*)(q1p + 16*ks + 2*l4);
            qa[ks][2] = *(const uint32_t*)(q0p + 16*ks + 2*l4 + 8);
            qa[ks][3] = *(const uint32_t*)(q1p + 16*ks + 2*l4 + 8);
        }
    }
    __syncwarp();

    float oacc[8][4];
#pragma unroll
    for (int nt = 0; nt < 8; nt++)
#pragma unroll
        for (int r = 0; r < 4; r++) oacc[nt][r] = 0.f;
    float mi0 = -1e30f, mi1 = -1e30f, li0 = 0.f, li1 = 0.f;

    const int wrmin = q0 + 16*w;
    const int wrmax = wrmin + 15;
    const int r0g   = wrmin + g;
    const int r1g   = r0g + 8;
    uint32_t* Pw0 = (uint32_t*)(Qs + (16*w + g)*ASTH);
    uint32_t* Pw1 = (uint32_t*)(Qs + (16*w + g + 8)*ASTH);

    for (int jt = jt0; jt <= jtmax; jt++) {
        const int kv0 = jt * 64;
        const int buf = jt & 1;
        cp_wait0();
        __syncthreads();

        if (jt < jtmax) {
            int r  = tid >> 2;
            int c0 = (tid & 3) * 2;
            int pos = kv0 + 64 + r;
            uint32_t kd = (uint32_t)__cvta_generic_to_shared(Ks + (buf^1)*64*ASTH + r*ASTH);
            uint32_t vd = (uint32_t)__cvta_generic_to_shared(Vs + (buf^1)*64*ASTH + r*ASTH);
            const __half* kp  = g_kh + (bT + pos)*CC + hoff;
            const __half* ksh = g_kh + (bT + pos - 1)*CC + hoff;
            const __half* vp  = g_vth + (vbase + r)*TT + kv0 + 64;
#pragma unroll
            for (int i = 0; i < 2; i++) {
                int c = c0 + i;
                const __half* kb = (c < 4) ? kp : ksh;
                cp_async16(kd + c*16, kb + c*8);
                cp_async16(vd + c*16, vp + c*8);
            }
            cp_commit();
        }

        bool dead = (kv0 > wrmax) || (use_w && (kv0 + 63 < wrmin - wsv));
        if (!dead) {
            const __half* Kb = Ks + buf*64*ASTH;
            const __half* Vb = Vs + buf*64*ASTH;

            float sacc[8][4];
#pragma unroll
            for (int nt = 0; nt < 8; nt++)
#pragma unroll
                for (int r = 0; r < 4; r++) sacc[nt][r] = 0.f;
#pragma unroll
            for (int ks = 0; ks < 4; ks++) {
#pragma unroll
                for (int nt = 0; nt < 8; nt++) {
                    const __half* kp2 = Kb + (8*nt + g)*ASTH + 16*ks + 2*l4;
                    uint32_t b0 = *(const uint32_t*)kp2;
                    uint32_t b1 = *(const uint32_t*)(kp2 + 8);
                    mma_fp16(sacc[nt], qa[ks][0], qa[ks][1], qa[ks][2], qa[ks][3], b0, b1);
                }
            }

            const bool full = (kv0 + 63 <= wrmin) &&
                              (!use_w || (wrmax - kv0 <= wsv));
            if (full) {
#pragma unroll
                for (int nt = 0; nt < 8; nt++)
#pragma unroll
                    for (int r = 0; r < 4; r++) sacc[nt][r] *= 0.125f;
            } else {
#pragma unroll
                for (int nt = 0; nt < 8; nt++) {
                    int c0 = kv0 + 8*nt + 2*l4;
#pragma unroll
                    for (int r = 0; r < 4; r++) {
                        int qi = (r < 2) ? r0g : r1g;
                        int kj = c0 + (r & 1);
                        bool ok = (kj <= qi) && (!use_w || (qi - kj) <= wsv);
                        sacc[nt][r] = ok ? sacc[nt][r]*0.125f : -1e30f;
                    }
                }
            }

            float mx0 = -1e30f, mx1 = -1e30f;
#pragma unroll
            for (int nt = 0; nt < 8; nt++) {
                mx0 = fmaxf(mx0, fmaxf(sacc[nt][0], sacc[nt][1]));
                mx1 = fmaxf(mx1, fmaxf(sacc[nt][2], sacc[nt][3]));
            }
            mx0 = fmaxf(mx0, __shfl_xor_sync(0xffffffffu, mx0, 1));
            mx0 = fmaxf(mx0, __shfl_xor_sync(0xffffffffu, mx0, 2));
            mx1 = fmaxf(mx1, __shfl_xor_sync(0xffffffffu, mx1, 1));
            mx1 = fmaxf(mx1, __shfl_xor_sync(0xffffffffu, mx1, 2));
            float mn0 = fmaxf(fmaxf(mi0, mx0), -1e29f);
            float mn1 = fmaxf(fmaxf(mi1, mx1), -1e29f);
            float corr0 = __expf(mi0 - mn0);
            float corr1 = __expf(mi1 - mn1);
            float sum0 = 0.f, sum1 = 0.f;
#pragma unroll
            for (int nt = 0; nt < 8; nt++) {
                float p0 = __expf(sacc[nt][0] - mn0);
                float p1 = __expf(sacc[nt][1] - mn0);
                float p2 = __expf(sacc[nt][2] - mn1);
                float p3 = __expf(sacc[nt][3] - mn1);
                sum0 += p0 + p1; sum1 += p2 + p3;
                __half2 hp0 = __floats2half2_rn(p0, p1);
                __half2 hp1 = __floats2half2_rn(p2, p3);
                Pw0[4*nt + l4] = *(uint32_t*)&hp0;
                Pw1[4*nt + l4] = *(uint32_t*)&hp1;
            }
            sum0 += __shfl_xor_sync(0xffffffffu, sum0, 1);
            sum0 += __shfl_xor_sync(0xffffffffu, sum0, 2);
            sum1 += __shfl_xor_sync(0xffffffffu, sum1, 1);
            sum1 += __shfl_xor_sync(0xffffffffu, sum1, 2);
            li0 = li0*corr0 + sum0;
            li1 = li1*corr1 + sum1;
            mi0 = mn0; mi1 = mn1;
#pragma unroll
            for (int nt = 0; nt < 8; nt++) {
                oacc[nt][0] *= corr0; oacc[nt][1] *= corr0;
                oacc[nt][2] *= corr1; oacc[nt][3] *= corr1;
            }
            __syncwarp();

#pragma unroll
            for (int ks = 0; ks < 4; ks++) {
                uint32_t a0 = Pw0[8*ks + l4];
                uint32_t a1 = Pw1[8*ks + l4];
                uint32_t a2 = Pw0[8*ks + l4 + 4];
                uint32_t a3 = Pw1[8*ks + l4 + 4];
#pragma unroll
                for (int nt = 0; nt < 8; nt++) {
                    const __half* vp2 = Vb + (8*nt + g)*ASTH + 16*ks + 2*l4;
                    uint32_t b0 = *(const uint32_t*)vp2;
                    uint32_t b1 = *(const uint32_t*)(vp2 + 8);
                    mma_fp16(oacc[nt], a0, a1, a2, a3, b0, b1);
                }
            }
            __syncwarp();
        }
    }

    float ga0 = g_ga[(bT + r0g)*HH + h];
    float ga1 = g_ga[(bT + r1g)*HH + h];
    float inv0 = ga0 / li0;
    float inv1 = ga1 / li1;
    __half* y0 = g_yh + (bT + r0g)*CC + hoff;
    __half* y1 = g_yh + (bT + r1g)*CC + hoff;
#pragma unroll
    for (int nt = 0; nt < 8; nt++) {
        int c = 8*nt + 2*l4;
        __half2 w0 = __floats2half2_rn(oacc[nt][0]*inv0, oacc[nt][1]*inv0);
        __half2 w1 = __floats2half2_rn(oacc[nt][2]*inv1, oacc[nt][3]*inv1);
        *(__half2*)(y0 + c) = w0;
        *(__half2*)(y1 + c) = w1;
    }
}

// ---------------- launch ----------------------------------------------------
extern "C" void kernel_launch(void* const* d_in, const int* in_sizes, int n_in,
                              void* d_out, int out_size) {
    const float* x    = (const float*)d_in[0];
    const float* ve   = (const float*)d_in[1];
    const float* cosb = (const float*)d_in[2];
    const float* sinb = (const float*)d_in[3];
    const float* cqw  = (const float*)d_in[4];
    const float* ckw  = (const float*)d_in[5];
    const float* cvw  = (const float*)d_in[6];
    const float* cpw  = (const float*)d_in[7];
    const float* vgw  = (const float*)d_in[8];
    const float* agw  = (const float*)d_in[9];
    const float* qm   = (const float*)d_in[10];
    const float* km   = (const float*)d_in[11];
    const float* vm   = (const float*)d_in[12];
    const int*   wsp  = (n_in > 13) ? (const int*)d_in[13] : nullptr;
    float* out = (float*)d_out;

    __half *pqwh, *pkwh, *pvwh, *ppwh, *pxh, *pyh, *pqh, *pkh, *pvh;
    cudaGetSymbolAddress((void**)&pqwh, g_qwh);
    cudaGetSymbolAddress((void**)&pkwh, g_kwh);
    cudaGetSymbolAddress((void**)&pvwh, g_vwh);
    cudaGetSymbolAddress((void**)&ppwh, g_pwh);
    cudaGetSymbolAddress((void**)&pxh,  g_xh);
    cudaGetSymbolAddress((void**)&pyh,  g_yh);
    cudaGetSymbolAddress((void**)&pqh,  g_qh);
    cudaGetSymbolAddress((void**)&pkh,  g_kh);
    cudaGetSymbolAddress((void**)&pvh,  g_vh);

    // 0) convert x to fp16
    round_x_kernel<<<NROWS*CC/1024, 256>>>(x);

    // 1) fuse mixes into weights (fp16) + convert cpw
    fuse_kernel<<<dim3(CC, 4), 256>>>(cqw, ckw, cvw, cpw, qm, km, vm);

    // 2) QKV projections (fp16 mma, fp16 output)
    cudaFuncSetAttribute(gemm_fp16_kernel<__half>,
                         cudaFuncAttributeMaxDynamicSharedMemorySize, GEMM_SMEM);
    cudaFuncSetAttribute(gemm_fp16_kernel<float>,
                         cudaFuncAttributeMaxDynamicSharedMemorySize, GEMM_SMEM);
    gemm_fp16_kernel<__half><<<dim3(NROWS/128, CC/128, 3), 256, GEMM_SMEM>>>(
        pxh, pqwh, pqh, pkwh, pkh, pvwh, pvh, CC);

    // 3) gates + rope + rmsnorm (fp16 in/out)
    post_kernel<<<(NROWS*HH*32)/256, 256>>>(x, ve, cosb, sinb, vgw, agw);

    // 3b) V transpose
    vtrans_kernel<<<dim3(TT/64, HH, BB), 256>>>();

    // 4) flash attention (fp16 mma)
    cudaFuncSetAttribute(attn_kernel, cudaFuncAttributeMaxDynamicSharedMemorySize, ATTN_SMEM);
    attn_kernel<<<dim3(TT/128, HH, BB), 256, ATTN_SMEM>>>(wsp);

    // 5) output projection (fp16 mma, fp32 output)
    gemm_fp16_kernel<float><<<dim3(NROWS/128, CC/128, 1), 256, GEMM_SMEM>>>(
        pyh, ppwh, out, ppwh, out, ppwh, out, CC);
}

// round 15
// speedup vs baseline: 2.0777x; 1.0364x over previous
#include <cuda_runtime.h>
#include <cuda_fp16.h>
#include <cstdint>
#include <cstddef>
#include <math.h>

#define BB 2
#define TT 2048
#define CC 1024
#define HH 16
#define NROWS (BB*TT)   // 4096

// ---------------- scratch (static device allocations; no cudaMalloc) -------
__device__ __half g_qwh[CC*CC];
__device__ __half g_kwh[CC*CC];
__device__ __half g_vwh[CC*CC];
__device__ __half g_pwh[CC*CC];
__device__ __half g_xh[NROWS*CC];
__device__ __half g_yh[NROWS*CC];
__device__ __half g_qh[NROWS*CC];
__device__ __half g_kh[NROWS*CC];
__device__ __half g_vh[NROWS*CC];
__device__ __half g_vth[(size_t)BB*HH*64*TT];   // V^T: [(b*HH+h)*64+d][t]
__device__ float  g_ga[NROWS*HH];

// ---------------- helpers ----------------------------------------------------
__device__ __forceinline__ void cp_async16(uint32_t saddr, const void* g) {
    asm volatile("cp.async.cg.shared.global [%0], [%1], 16;\n" :: "r"(saddr), "l"(g));
}
__device__ __forceinline__ void cp_commit() {
    asm volatile("cp.async.commit_group;\n");
}
__device__ __forceinline__ void cp_wait0() {
    asm volatile("cp.async.wait_group 0;\n");
}
__device__ __forceinline__ void cp_wait1() {
    asm volatile("cp.async.wait_group 1;\n");
}
__device__ __forceinline__ void mma_fp16(float c[4], uint32_t a0, uint32_t a1,
                                         uint32_t a2, uint32_t a3,
                                         uint32_t b0, uint32_t b1) {
    asm volatile(
        "mma.sync.aligned.m16n8k16.row.col.f32.f16.f16.f32 "
        "{%0,%1,%2,%3}, {%4,%5,%6,%7}, {%8,%9}, {%0,%1,%2,%3};"
        : "+f"(c[0]), "+f"(c[1]), "+f"(c[2]), "+f"(c[3])
        : "r"(a0), "r"(a1), "r"(a2), "r"(a3), "r"(b0), "r"(b1));
}

// ---------------- 1) fuse mix -> fp16 weights; wi=3 cpw; wi=4 converts x ----
__global__ void fuse_kernel(const float* __restrict__ x,
                            const float* __restrict__ cq, const float* __restrict__ ck,
                            const float* __restrict__ cv, const float* __restrict__ cp,
                            const float* __restrict__ qm,
                            const float* __restrict__ km, const float* __restrict__ vm) {
    int row = blockIdx.x;
    int wi  = blockIdx.y;
    int c = threadIdx.x * 4;
    if (wi == 4) {
        // convert 4 rows of x (NROWS = 4*gridDim.x)
#pragma unroll
        for (int rr = 0; rr < 4; rr++) {
            size_t off = (size_t)(row*4 + rr)*CC + c;
            float4 v = *(const float4*)&x[off];
            __half2 h0 = __floats2half2_rn(v.x, v.y);
            __half2 h1 = __floats2half2_rn(v.z, v.w);
            uint2 r = {*(uint32_t*)&h0, *(uint32_t*)&h1};
            *(uint2*)&g_xh[off] = r;
        }
        return;
    }
    if (wi == 3) {
        float4 v = *(const float4*)&cp[row*CC + c];
        __half2 h0 = __floats2half2_rn(v.x, v.y);
        __half2 h1 = __floats2half2_rn(v.z, v.w);
        uint2 r = {*(uint32_t*)&h0, *(uint32_t*)&h1};
        *(uint2*)&g_pwh[row*CC + c] = r;
        return;
    }
    const float* W = (wi == 0) ? cq : (wi == 1) ? ck : cv;
    const float* M = (wi == 0) ? qm : (wi == 1) ? km : vm;
    __half* O      = (wi == 0) ? g_qwh : (wi == 1) ? g_kwh : g_vwh;
    int h = row >> 6, d = row & 63;
    float mx[16];
#pragma unroll
    for (int m = 0; m < 16; m++) mx[m] = M[h*16 + m];
    float4 s = {0.f, 0.f, 0.f, 0.f};
#pragma unroll
    for (int m = 0; m < 16; m++) {
        float4 w = *(const float4*)&W[(size_t)(m*64 + d)*CC + c];
        s.x += mx[m]*w.x; s.y += mx[m]*w.y;
        s.z += mx[m]*w.z; s.w += mx[m]*w.w;
    }
    __half2 h0 = __floats2half2_rn(s.x, s.y);
    __half2 h1 = __floats2half2_rn(s.z, s.w);
    uint2 r = {*(uint32_t*)&h0, *(uint32_t*)&h1};
    *(uint2*)&O[row*CC + c] = r;
}

// ---------------- 2) NT GEMM, fp16 m16n8k16, BK=32, 3-stage; output T -------
#define HST 40
#define HSTG (128*HST)
#define GEMM_SMEM (3*2*HSTG*2)

template <typename TO>
__global__ __launch_bounds__(256, 2) void gemm_fp16_kernel(
    const __half* __restrict__ A,
    const __half* __restrict__ B0, TO* __restrict__ C0,
    const __half* __restrict__ B1, TO* __restrict__ C1,
    const __half* __restrict__ B2, TO* __restrict__ C2,
    int K) {
    const __half* Bm = (blockIdx.z == 0) ? B0 : (blockIdx.z == 1) ? B1 : B2;
    TO*           Cm = (blockIdx.z == 0) ? C0 : (blockIdx.z == 1) ? C1 : C2;
    const int N = CC;

    extern __shared__ __half hsm[];
    __half* Asm = hsm;
    __half* Bsm = hsm + 3*HSTG;

    const int tid  = threadIdx.x;
    const int lane = tid & 31;
    const int warp = tid >> 5;
    const int wr = warp & 1;
    const int wc = warp >> 1;
    const int g  = lane >> 2;
    const int l4 = lane & 3;
    const int brow = blockIdx.x * 128, bcol = blockIdx.y * 128;

    const int lrow = tid >> 1;
    const int lch  = (tid & 1) * 16;
    const __half* Ab = A  + (size_t)(brow + lrow) * K + lch;
    const __half* Bb = Bm + (size_t)(bcol + lrow) * K + lch;
    const uint32_t Ad = (uint32_t)__cvta_generic_to_shared(Asm + lrow*HST + lch);
    const uint32_t Bd = (uint32_t)__cvta_generic_to_shared(Bsm + lrow*HST + lch);
    const uint32_t stageB = HSTG * 2;

    const int NIT = K / 32;

#pragma unroll
    for (int s = 0; s < 2; s++) {
        cp_async16(Ad + s*stageB,      Ab + s*32);
        cp_async16(Ad + s*stageB + 16, Ab + s*32 + 8);
        cp_async16(Bd + s*stageB,      Bb + s*32);
        cp_async16(Bd + s*stageB + 16, Bb + s*32 + 8);
        cp_commit();
    }

    float acc[4][4][4];
#pragma unroll
    for (int mi = 0; mi < 4; mi++)
#pragma unroll
        for (int ni = 0; ni < 4; ni++)
#pragma unroll
            for (int r = 0; r < 4; r++) acc[mi][ni][r] = 0.f;

    for (int it = 0; it < NIT; it++) {
        if (it + 1 < NIT) cp_wait1(); else cp_wait0();
        __syncthreads();
        if (it + 2 < NIT) {
            int s = (it + 2) % 3;
            cp_async16(Ad + s*stageB,      Ab + (it+2)*32);
            cp_async16(Ad + s*stageB + 16, Ab + (it+2)*32 + 8);
            cp_async16(Bd + s*stageB,      Bb + (it+2)*32);
            cp_async16(Bd + s*stageB + 16, Bb + (it+2)*32 + 8);
            cp_commit();
        }
        const uint32_t* Aw = (const uint32_t*)(Asm + (it % 3)*HSTG);
        const uint32_t* Bw = (const uint32_t*)(Bsm + (it % 3)*HSTG);
#pragma unroll
        for (int ks = 0; ks < 2; ks++) {
            const int k0w = ks*8;
            uint32_t bf[4][2];
#pragma unroll
            for (int ni = 0; ni < 4; ni++) {
                const uint32_t* bp = Bw + (wc*32 + ni*8 + g)*20 + k0w + l4;
                bf[ni][0] = bp[0];
                bf[ni][1] = bp[4];
            }
#pragma unroll
            for (int mi = 0; mi < 4; mi++) {
                const uint32_t* ap0 = Aw + (wr*64 + mi*16 + g)*20 + k0w + l4;
                const uint32_t* ap1 = ap0 + 8*20;
                uint32_t a0 = ap0[0];
                uint32_t a1 = ap1[0];
                uint32_t a2 = ap0[4];
                uint32_t a3 = ap1[4];
#pragma unroll
                for (int ni = 0; ni < 4; ni++)
                    mma_fp16(acc[mi][ni], a0, a1, a2, a3, bf[ni][0], bf[ni][1]);
            }
        }
    }

#pragma unroll
    for (int mi = 0; mi < 4; mi++) {
#pragma unroll
        for (int ni = 0; ni < 4; ni++) {
            int row0 = brow + wr*64 + mi*16 + g;
            int col  = bcol + wc*32 + ni*8 + 2*l4;
            if (sizeof(TO) == 4) {
                float2 w0 = {acc[mi][ni][0], acc[mi][ni][1]};
                float2 w1 = {acc[mi][ni][2], acc[mi][ni][3]};
                *(float2*)((float*)Cm + (size_t)row0 * N + col)       = w0;
                *(float2*)((float*)Cm + (size_t)(row0 + 8) * N + col) = w1;
            } else {
                __half2 w0 = __floats2half2_rn(acc[mi][ni][0], acc[mi][ni][1]);
                __half2 w1 = __floats2half2_rn(acc[mi][ni][2], acc[mi][ni][3]);
                *(__half2*)((__half*)Cm + (size_t)row0 * N + col)       = w0;
                *(__half2*)((__half*)Cm + (size_t)(row0 + 8) * N + col) = w1;
            }
        }
    }
}

// ---------------- 3) gates + RoPE + RMSNorm; fp16 in/out --------------------
__global__ void post_kernel(const float* __restrict__ x, const float* __restrict__ ve,
                            const float* __restrict__ cosb, const float* __restrict__ sinb,
                            const float* __restrict__ vgw, const float* __restrict__ agw) {
    int gw   = (blockIdx.x * blockDim.x + threadIdx.x) >> 5;
    int lane = threadIdx.x & 31;
    if (gw >= NROWS*HH) return;
    int h  = gw % HH;
    int bt = gw / HH;
    int t  = bt % TT;
    size_t xbase = (size_t)bt * CC;

    float gv = x[xbase + lane] * vgw[h*32 + lane];
#pragma unroll
    for (int o = 16; o > 0; o >>= 1) gv += __shfl_xor_sync(0xffffffffu, gv, o);
    float gate_v = 2.f / (1.f + __expf(-gv));

    float ga = (lane < 12) ? x[xbase + lane] * agw[h*12 + lane] : 0.f;
#pragma unroll
    for (int o = 16; o > 0; o >>= 1) ga += __shfl_xor_sync(0xffffffffu, ga, o);
    if (lane == 0) g_ga[(size_t)bt*HH + h] = 1.f / (1.f + __expf(-ga));

    size_t idx = xbase + h*64;
    float v1 = __half2float(g_vh[idx + lane])      + gate_v * ve[idx + lane];
    float v2 = __half2float(g_vh[idx + lane + 32]) + gate_v * ve[idx + lane + 32];
    g_vh[idx + lane]      = __float2half_rn(v1);
    g_vh[idx + lane + 32] = __float2half_rn(v2);

    float cs = cosb[t*32 + lane], sn = sinb[t*32 + lane];
    {
        float q1 = __half2float(g_qh[idx + lane]);
        float q2 = __half2float(g_qh[idx + lane + 32]);
        float r1 =  q1*cs + q2*sn;
        float r2 = -q1*sn + q2*cs;
        float ss = r1*r1 + r2*r2;
#pragma unroll
        for (int o = 16; o > 0; o >>= 1) ss += __shfl_xor_sync(0xffffffffu, ss, o);
        float sc = rsqrtf(ss * (1.f/64.f) + 1e-6f);
        g_qh[idx + lane]      = __float2half_rn(r1*sc);
        g_qh[idx + lane + 32] = __float2half_rn(r2*sc);
    }
    {
        float k1 = __half2float(g_kh[idx + lane]);
        float k2 = __half2float(g_kh[idx + lane + 32]);
        float r1 =  k1*cs + k2*sn;
        float r2 = -k1*sn + k2*cs;
        float ss = r1*r1 + r2*r2;
#pragma unroll
        for (int o = 16; o > 0; o >>= 1) ss += __shfl_xor_sync(0xffffffffu, ss, o);
        float sc = rsqrtf(ss * (1.f/64.f) + 1e-6f);
        g_kh[idx + lane]      = __float2half_rn(r1*sc);
        g_kh[idx + lane + 32] = __float2half_rn(r2*sc);
    }
}

// ---------------- 3b) transpose V -> V^T (fp16) ------------------------------
__global__ void vtrans_kernel() {
    __shared__ __half ts[64][65];
    const int tbk = blockIdx.x, h = blockIdx.y, b = blockIdx.z;
    const int tid = threadIdx.x;
    const size_t bT = (size_t)b*TT;
    const int t0 = tbk*64;
#pragma unroll
    for (int i = 0; i < 8; i++) {
        int w = tid + i*256;
        int t = w >> 5, dp = w & 31;
        uint32_t v = *(const uint32_t*)(g_vh + (bT + t0 + t)*CC + h*64 + 2*dp);
        __half2 hv = *(__half2*)&v;
        ts[2*dp][t]   = __low2half(hv);
        ts[2*dp+1][t] = __high2half(hv);
    }
    __syncthreads();
    const size_t vbase = ((size_t)(b*HH + h))*64;
#pragma unroll
    for (int i = 0; i < 8; i++) {
        int w = tid + i*256;
        int d = w >> 5, tp = w & 31;
        __half2 hv = __halves2half2(ts[d][2*tp], ts[d][2*tp+1]);
        *(uint32_t*)(g_vth + (vbase + d)*TT + t0 + 2*tp) = *(uint32_t*)&hv;
    }
}

// ---------------- 4) flash attention, fp16 mma, no-max softmax --------------
// RMSNorm bounds |q|,|k| <= 8 => s = q.k/8 in [-8,8]; exp(s) <= 2981 fits fp16,
// sum < 6.2e6 fits fp32 -> online max tracking dropped entirely.
#define ASTH 72
#define ATTN_SMEM ((128*ASTH + 4*64*ASTH)*2)   // 55296 B

__global__ __launch_bounds__(256, 2) void attn_kernel(const int* __restrict__ wsp) {
    extern __shared__ __half ash[];
    __half* Qs = ash;
    __half* Ks = ash + 128*ASTH;
    __half* Vs = Ks  + 2*64*ASTH;

    const int qtb = (TT/128 - 1) - blockIdx.x;
    const int h = blockIdx.y, b = blockIdx.z;
    const int tid  = threadIdx.x;
    const int lane = tid & 31;
    const int w    = tid >> 5;
    const int g    = lane >> 2;
    const int l4   = lane & 3;
    const int q0   = qtb * 128;
    const int hoff = h*64;
    const size_t bT = (size_t)b*TT;
    const size_t vbase = ((size_t)(b*HH + h))*64;

    int wsv = wsp ? *wsp : -1;
    const bool use_w = (wsv >= 0) && (wsv < TT - 1);
    int jt0 = 0;
    if (use_w) {
        int lo = q0 - wsv - 63;
        if (lo > 0) jt0 = (lo + 63) >> 6;
    }
    const int jtmax = 2*qtb + 1;

    {
        int row = tid >> 1;
        int c0  = (tid & 1) * 4;
        const __half* src = g_qh + (bT + q0 + row)*CC + hoff;
        uint32_t dst = (uint32_t)__cvta_generic_to_shared(Qs + row*ASTH);
#pragma unroll
        for (int i = 0; i < 4; i++) cp_async16(dst + (c0 + i)*16, src + (c0 + i)*8);
        cp_commit();
    }
    {
        int r  = tid >> 2;
        int c0 = (tid & 3) * 2;
        int pos = jt0*64 + r;
        int sh  = (pos > 0) ? pos - 1 : 0;
        uint32_t kd = (uint32_t)__cvta_generic_to_shared(Ks + (jt0&1)*64*ASTH + r*ASTH);
        uint32_t vd = (uint32_t)__cvta_generic_to_shared(Vs + (jt0&1)*64*ASTH + r*ASTH);
        const __half* kp  = g_kh + (bT + pos)*CC + hoff;
        const __half* ksh = g_kh + (bT + sh)*CC + hoff;
        const __half* vp  = g_vth + (vbase + r)*TT + jt0*64;
#pragma unroll
        for (int i = 0; i < 2; i++) {
            int c = c0 + i;
            const __half* kb = (c < 4) ? kp : ksh;
            cp_async16(kd + c*16, kb + c*8);
            cp_async16(vd + c*16, vp + c*8);
        }
        cp_commit();
    }

    uint32_t qa[4][4];
    cp_wait1();
    __syncthreads();
    {
        const __half* q0p = Qs + (16*w + g)*ASTH;
        const __half* q1p = q0p + 8*ASTH;
#pragma unroll
        for (int ks = 0; ks < 4; ks++) {
            qa[ks][0] = *(const uint32_t*)(q0p + 16*ks + 2*l4);
            qa[ks][1] = *(const uint32_t*)(q1p + 16*ks + 2*l4);
            qa[ks][2] = *(const uint32_t*)(q0p + 16*ks + 2*l4 + 8);
            qa[ks][3] = *(const uint32_t*)(q1p + 16*ks + 2*l4 + 8);
        }
    }
    __syncwarp();

    float oacc[8][4];
#pragma unroll
    for (int nt = 0; nt < 8; nt++)
#pragma unroll
        for (int r = 0; r < 4; r++) oacc[nt][r] = 0.f;
    float li0 = 0.f, li1 = 0.f;

    const int wrmin = q0 + 16*w;
    const int wrmax = wrmin + 15;
    const int r0g   = wrmin + g;
    const int r1g   = r0g + 8;
    uint32_t* Pw0 = (uint32_t*)(Qs + (16*w + g)*ASTH);
    uint32_t* Pw1 = (uint32_t*)(Qs + (16*w + g + 8)*ASTH);

    for (int jt = jt0; jt <= jtmax; jt++) {
        const int kv0 = jt * 64;
        const int buf = jt & 1;
        cp_wait0();
        __syncthreads();

        if (jt < jtmax) {
            int r  = tid >> 2;
            int c0 = (tid & 3) * 2;
            int pos = kv0 + 64 + r;
            uint32_t kd = (uint32_t)__cvta_generic_to_shared(Ks + (buf^1)*64*ASTH + r*ASTH);
            uint32_t vd = (uint32_t)__cvta_generic_to_shared(Vs + (buf^1)*64*ASTH + r*ASTH);
            const __half* kp  = g_kh + (bT + pos)*CC + hoff;
            const __half* ksh = g_kh + (bT + pos - 1)*CC + hoff;
            const __half* vp  = g_vth + (vbase + r)*TT + kv0 + 64;
#pragma unroll
            for (int i = 0; i < 2; i++) {
                int c = c0 + i;
                const __half* kb = (c < 4) ? kp : ksh;
                cp_async16(kd + c*16, kb + c*8);
                cp_async16(vd + c*16, vp + c*8);
            }
            cp_commit();
        }

        bool dead = (kv0 > wrmax) || (use_w && (kv0 + 63 < wrmin - wsv));
        if (!dead) {
            const __half* Kb = Ks + buf*64*ASTH;
            const __half* Vb = Vs + buf*64*ASTH;

            float sacc[8][4];
#pragma unroll
            for (int nt = 0; nt < 8; nt++)
#pragma unroll
                for (int r = 0; r < 4; r++) sacc[nt][r] = 0.f;
#pragma unroll
            for (int ks = 0; ks < 4; ks++) {
#pragma unroll
                for (int nt = 0; nt < 8; nt++) {
                    const __half* kp2 = Kb + (8*nt + g)*ASTH + 16*ks + 2*l4;
                    uint32_t b0 = *(const uint32_t*)kp2;
                    uint32_t b1 = *(const uint32_t*)(kp2 + 8);
                    mma_fp16(sacc[nt], qa[ks][0], qa[ks][1], qa[ks][2], qa[ks][3], b0, b1);
                }
            }

            const bool full = (kv0 + 63 <= wrmin) &&
                              (!use_w || (wrmax - kv0 <= wsv));
            if (full) {
#pragma unroll
                for (int nt = 0; nt < 8; nt++)
#pragma unroll
                    for (int r = 0; r < 4; r++) sacc[nt][r] *= 0.125f;
            } else {
#pragma unroll
                for (int nt = 0; nt < 8; nt++) {
                    int c0 = kv0 + 8*nt + 2*l4;
#pragma unroll
                    for (int r = 0; r < 4; r++) {
                        int qi = (r < 2) ? r0g : r1g;
                        int kj = c0 + (r & 1);
                        bool ok = (kj <= qi) && (!use_w || (qi - kj) <= wsv);
                        sacc[nt][r] = ok ? sacc[nt][r]*0.125f : -1e30f;
                    }
                }
            }

            // no-max softmax: p = exp(s), masked -> exp(-1.25e29) = 0
            float sum0 = 0.f, sum1 = 0.f;
#pragma unroll
            for (int nt = 0; nt < 8; nt++) {
                float p0 = __expf(sacc[nt][0]);
                float p1 = __expf(sacc[nt][1]);
                float p2 = __expf(sacc[nt][2]);
                float p3 = __expf(sacc[nt][3]);
                sum0 += p0 + p1; sum1 += p2 + p3;
                __half2 hp0 = __floats2half2_rn(p0, p1);
                __half2 hp1 = __floats2half2_rn(p2, p3);
                Pw0[4*nt + l4] = *(uint32_t*)&hp0;
                Pw1[4*nt + l4] = *(uint32_t*)&hp1;
            }
            sum0 += __shfl_xor_sync(0xffffffffu, sum0, 1);
            sum0 += __shfl_xor_sync(0xffffffffu, sum0, 2);
            sum1 += __shfl_xor_sync(0xffffffffu, sum1, 1);
            sum1 += __shfl_xor_sync(0xffffffffu, sum1, 2);
            li0 += sum0;
            li1 += sum1;
            __syncwarp();

#pragma unroll
            for (int ks = 0; ks < 4; ks++) {
                uint32_t a0 = Pw0[8*ks + l4];
                uint32_t a1 = Pw1[8*ks + l4];
                uint32_t a2 = Pw0[8*ks + l4 + 4];
                uint32_t a3 = Pw1[8*ks + l4 + 4];
#pragma unroll
                for (int nt = 0; nt < 8; nt++) {
                    const __half* vp2 = Vb + (8*nt + g)*ASTH + 16*ks + 2*l4;
                    uint32_t b0 = *(const uint32_t*)vp2;
                    uint32_t b1 = *(const uint32_t*)(vp2 + 8);
                    mma_fp16(oacc[nt], a0, a1, a2, a3, b0, b1);
                }
            }
            __syncwarp();
        }
    }

    float ga0 = g_ga[(bT + r0g)*HH + h];
    float ga1 = g_ga[(bT + r1g)*HH + h];
    float inv0 = ga0 / li0;
    float inv1 = ga1 / li1;
    __half* y0 = g_yh + (bT + r0g)*CC + hoff;
    __half* y1 = g_yh + (bT + r1g)*CC + hoff;
#pragma unroll
    for (int nt = 0; nt < 8; nt++) {
        int c = 8*nt + 2*l4;
        __half2 w0 = __floats2half2_rn(oacc[nt][0]*inv0, oacc[nt][1]*inv0);
        __half2 w1 = __floats2half2_rn(oacc[nt][2]*inv1, oacc[nt][3]*inv1);
        *(__half2*)(y0 + c) = w0;
        *(__half2*)(y1 + c) = w1;
    }
}

// ---------------- launch ----------------------------------------------------
extern "C" void kernel_launch(void* const* d_in, const int* in_sizes, int n_in,
                              void* d_out, int out_size) {
    const float* x    = (const float*)d_in[0];
    const float* ve   = (const float*)d_in[1];
    const float* cosb = (const float*)d_in[2];
    const float* sinb = (const float*)d_in[3];
    const float* cqw  = (const float*)d_in[4];
    const float* ckw  = (const float*)d_in[5];
    const float* cvw  = (const float*)d_in[6];
    const float* cpw  = (const float*)d_in[7];
    const float* vgw  = (const float*)d_in[8];
    const float* agw  = (const float*)d_in[9];
    const float* qm   = (const float*)d_in[10];
    const float* km   = (const float*)d_in[11];
    const float* vm   = (const float*)d_in[12];
    const int*   wsp  = (n_in > 13) ? (const int*)d_in[13] : nullptr;
    float* out = (float*)d_out;

    __half *pqwh, *pkwh, *pvwh, *ppwh, *pxh, *pyh, *pqh, *pkh, *pvh;
    cudaGetSymbolAddress((void**)&pqwh, g_qwh);
    cudaGetSymbolAddress((void**)&pkwh, g_kwh);
    cudaGetSymbolAddress((void**)&pvwh, g_vwh);
    cudaGetSymbolAddress((void**)&ppwh, g_pwh);
    cudaGetSymbolAddress((void**)&pxh,  g_xh);
    cudaGetSymbolAddress((void**)&pyh,  g_yh);
    cudaGetSymbolAddress((void**)&pqh,  g_qh);
    cudaGetSymbolAddress((void**)&pkh,  g_kh);
    cudaGetSymbolAddress((void**)&pvh,  g_vh);

    // 1) fuse mixes + convert cpw + convert x (one launch)
    fuse_kernel<<<dim3(CC, 5), 256>>>(x, cqw, ckw, cvw, cpw, qm, km, vm);

    // 2) QKV projections (fp16 mma, fp16 output)
    cudaFuncSetAttribute(gemm_fp16_kernel<__half>,
                         cudaFuncAttributeMaxDynamicSharedMemorySize, GEMM_SMEM);
    cudaFuncSetAttribute(gemm_fp16_kernel<float>,
                         cudaFuncAttributeMaxDynamicSharedMemorySize, GEMM_SMEM);
    gemm_fp16_kernel<__half><<<dim3(NROWS/128, CC/128, 3), 256, GEMM_SMEM>>>(
        pxh, pqwh, pqh, pkwh, pkh, pvwh, pvh, CC);

    // 3) gates + rope + rmsnorm (fp16 in/out)
    post_kernel<<<(NROWS*HH*32)/256, 256>>>(x, ve, cosb, sinb, vgw, agw);

    // 3b) V transpose
    vtrans_kernel<<<dim3(TT/64, HH, BB), 256>>>();

    // 4) flash attention (fp16 mma, no-max softmax)
    cudaFuncSetAttribute(attn_kernel, cudaFuncAttributeMaxDynamicSharedMemorySize, ATTN_SMEM);
    attn_kernel<<<dim3(TT/128, HH, BB), 256, ATTN_SMEM>>>(wsp);

    // 5) output projection (fp16 mma, fp32 output)
    gemm_fp16_kernel<float><<<dim3(NROWS/128, CC/128, 1), 256, GEMM_SMEM>>>(
        pyh, ppwh, out, ppwh, out, ppwh, out, CC);
}